// round 12
// baseline (speedup 1.0000x reference)
#include <cuda_runtime.h>
#include <cuda_fp16.h>
#include <math.h>
#include <stdint.h>

#define NB    4
#define NTOK  4096
#define CDIM  1024
#define NH    16
#define HD    64
#define NBH   64
#define MTOT  16384
#define KDIM  1024
#define NQKV  3072

// GEMM tiling: single-pass fp16, 3-stage pipeline, 4 warps x (64x64) tile
#define BM 128
#define BN 128
#define BK 64
#define NCHUNK (KDIM / BK)      // 16
#define TILE_BYTES (128 * 128)              // 16384
#define OFF_A 0
#define OFF_B TILE_BYTES
#define STAGE_BYTES (2 * TILE_BYTES)        // 32768
#define NSTAGE 3
#define SMEM_GEMM_BYTES (NSTAGE * STAGE_BYTES)  // 98304

// SW128 swizzle
#define SWZ(o) ((o) ^ (((o) >> 3) & 0x70))

#define KVSPLIT 16
#define KV_STAGE 16384
#define SMEM_KV_BYTES (2 * KV_STAGE + 1024)   // 33792

// attn kernel smem offsets
#define AT_Q    0
#define AT_KV   16384
#define AT_KSUM 24576
#define AT_INV  24832
#define SMEM_AT_BYTES 25344

// ---------------------------------------------------------------------------
// Scratch (device globals)
// ---------------------------------------------------------------------------
__device__ __half g_x16[MTOT * KDIM];
__device__ __half g_wqkv[NQKV * KDIM];
__device__ __half g_wproj[CDIM * KDIM];
__device__ __half g_q16[NBH * NTOK * HD];
__device__ __half g_k16[NBH * NTOK * HD];
__device__ __half g_v[NBH * NTOK * HD];
__device__ float g_kv_part[KVSPLIT * NBH * HD * HD];
__device__ float g_ksum_part[KVSPLIT * NBH * HD];
__device__ float g_ksum[NBH * HD];
__device__ __half g_kvT[NBH * HD * HD];
__device__ __half g_attn[MTOT * CDIM];

__device__ __forceinline__ float elu1(float x) {
    return x > 0.f ? x + 1.f : expf(x);
}

// ---------------------------------------------------------------------------
// PTX helpers (compute_103-safe)
// ---------------------------------------------------------------------------
__device__ __forceinline__ uint32_t smem_u32(const void* p) {
    uint32_t a;
    asm("{ .reg .u64 t; cvta.to.shared.u64 t, %1; cvt.u32.u64 %0, t; }" : "=r"(a) : "l"(p));
    return a;
}
__device__ __forceinline__ void cp16(uint32_t s, const void* g) {
    asm volatile("cp.async.cg.shared.global [%0], [%1], 16;" :: "r"(s), "l"(g));
}
#define CP_COMMIT() asm volatile("cp.async.commit_group;" ::: "memory")
#define CP_WAIT1()  asm volatile("cp.async.wait_group 1;" ::: "memory")
#define CP_WAIT0()  asm volatile("cp.async.wait_group 0;" ::: "memory")

__device__ __forceinline__ void ldm4(uint32_t* r, uint32_t addr) {
    asm volatile("ldmatrix.sync.aligned.m8n8.x4.shared.b16 {%0,%1,%2,%3}, [%4];"
                 : "=r"(r[0]), "=r"(r[1]), "=r"(r[2]), "=r"(r[3]) : "r"(addr));
}
__device__ __forceinline__ void ldm4t(uint32_t* r, uint32_t addr) {
    asm volatile("ldmatrix.sync.aligned.m8n8.x4.trans.shared.b16 {%0,%1,%2,%3}, [%4];"
                 : "=r"(r[0]), "=r"(r[1]), "=r"(r[2]), "=r"(r[3]) : "r"(addr));
}
__device__ __forceinline__ void mma16816(float* d, const uint32_t* a,
                                         uint32_t b0, uint32_t b1) {
    asm volatile(
        "mma.sync.aligned.m16n8k16.row.col.f32.f16.f16.f32 "
        "{%0,%1,%2,%3}, {%4,%5,%6,%7}, {%8,%9}, {%0,%1,%2,%3};"
        : "+f"(d[0]), "+f"(d[1]), "+f"(d[2]), "+f"(d[3])
        : "r"(a[0]), "r"(a[1]), "r"(a[2]), "r"(a[3]), "r"(b0), "r"(b1));
}

// ---------------------------------------------------------------------------
// GEMM stage loader (A, B): 128x64 fp16 tiles, SW128 rows. 128 threads,
// 16 cp16 per thread.
// ---------------------------------------------------------------------------
__device__ __forceinline__ void load_stage(
    uint32_t sbase,
    const __half* __restrict__ A, const __half* __restrict__ B,
    int m0, int n0, int kc, int tid)
{
#pragma unroll
    for (int t = 0; t < 8; t++) {
        int idx = t * 128 + tid;
        int row = idx >> 3;
        int c16 = idx & 7;
        uint32_t so = SWZ((uint32_t)(row * 128 + c16 * 16));
        cp16(sbase + OFF_A + so, A + (size_t)(m0 + row) * KDIM + kc + c16 * 8);
        cp16(sbase + OFF_B + so, B + (size_t)(n0 + row) * KDIM + kc + c16 * 8);
    }
}

// ---------------------------------------------------------------------------
// GEMM mainloop: 4 warps, warp tile 64x64, acc[4][8][4] += A*B over K=1024.
// Per k16 step: 8 ldm4 feed 32 HMMA (1.5x less smem traffic per MMA than
// the 32x64 warp tile).
// ---------------------------------------------------------------------------
__device__ __forceinline__ void mma_mainloop(
    const __half* __restrict__ A, const __half* __restrict__ B,
    int m0, int n0, uint32_t sm32, float acc[4][8][4])
{
    const int tid = threadIdx.x;
    const int lane = tid & 31;
    const int wid = tid >> 5;
    const int wm = wid & 1;        // 2 warps over M (64 rows each)
    const int wn = wid >> 1;       // 2 warps over N (64 cols each)

    load_stage(sm32, A, B, m0, n0, 0, tid);
    CP_COMMIT();
    load_stage(sm32 + STAGE_BYTES, A, B, m0, n0, BK, tid);
    CP_COMMIT();

    const int a_row = (lane & 15);
    const int a_koff = (lane & 16) ? 8 : 0;
    const int b_row = (lane & 7) + ((lane & 16) >> 1);
    const int b_koff = (lane & 8) ? 8 : 0;

    uint32_t aoffs[4], boffs[4];
#pragma unroll
    for (int ma = 0; ma < 4; ma++)
        aoffs[ma] = (uint32_t)((wm * 64 + ma * 16 + a_row) * 128 + a_koff * 2);
#pragma unroll
    for (int nb = 0; nb < 4; nb++)
        boffs[nb] = (uint32_t)((wn * 64 + nb * 16 + b_row) * 128 + b_koff * 2);

    int cur = 0, pre = 2;
    for (int c = 0; c < NCHUNK; c++) {
        if (c == NCHUNK - 1) CP_WAIT0(); else CP_WAIT1();
        __syncthreads();

        if (c + 2 < NCHUNK) {
            load_stage(sm32 + pre * STAGE_BYTES, A, B, m0, n0, (c + 2) * BK, tid);
            CP_COMMIT();
        }

        const uint32_t sb = sm32 + cur * STAGE_BYTES;
#pragma unroll
        for (int kk = 0; kk < BK; kk += 16) {
            uint32_t aa[4][4], bb[4][4];
            const uint32_t kb = (uint32_t)(kk * 2);
#pragma unroll
            for (int ma = 0; ma < 4; ma++)
                ldm4(aa[ma], sb + OFF_A + SWZ(aoffs[ma] + kb));
#pragma unroll
            for (int nb = 0; nb < 4; nb++)
                ldm4(bb[nb], sb + OFF_B + SWZ(boffs[nb] + kb));
#pragma unroll
            for (int ma = 0; ma < 4; ma++)
#pragma unroll
                for (int na = 0; na < 8; na++)
                    mma16816(acc[ma][na], aa[ma],
                             bb[na >> 1][(na & 1) * 2], bb[na >> 1][(na & 1) * 2 + 1]);
        }
        cur = (cur == NSTAGE - 1) ? 0 : cur + 1;
        pre = (pre == NSTAGE - 1) ? 0 : pre + 1;
    }
}

// ---------------------------------------------------------------------------
// QKV GEMM: epilogue applies elu+1 to q,k; writes q,k,v single fp16.
// ---------------------------------------------------------------------------
__global__ __launch_bounds__(128, 2) void gemm_qkv_mma() {
    extern __shared__ char smem[];
    const uint32_t sm32 = smem_u32(smem);
    const int m0 = blockIdx.y * BM;
    const int n0 = blockIdx.x * BN;

    float acc[4][8][4];
#pragma unroll
    for (int i = 0; i < 4; i++)
#pragma unroll
        for (int j = 0; j < 8; j++)
#pragma unroll
            for (int k = 0; k < 4; k++) acc[i][j][k] = 0.f;

    mma_mainloop(g_x16, g_wqkv, m0, n0, sm32, acc);

    const int tid = threadIdx.x;
    const int lane = tid & 31;
    const int wid = tid >> 5;
    const int wm = wid & 1, wn = wid >> 1;
    const int r0 = lane >> 2;
    const int c0 = (lane & 3) * 2;

#pragma unroll
    for (int ma = 0; ma < 4; ma++) {
#pragma unroll
        for (int na = 0; na < 8; na++) {
            const int colg = n0 + wn * 64 + na * 8 + c0;
            const int part = colg >> 10;
            const int h = (colg & 1023) >> 6;
            const int d = colg & 63;
            __half* dst = (part == 0) ? g_q16 : (part == 1) ? g_k16 : g_v;
            const bool feat = part < 2;
#pragma unroll
            for (int hf = 0; hf < 2; hf++) {
                const int m = m0 + wm * 64 + ma * 16 + r0 + hf * 8;
                const int bb = m >> 12, t = m & 4095;
                float v0 = acc[ma][na][hf * 2 + 0];
                float v1 = acc[ma][na][hf * 2 + 1];
                if (feat) { v0 = elu1(v0); v1 = elu1(v1); }
                size_t off = ((size_t)(bb * NH + h) * NTOK + t) * HD + d;
                *(__half2*)(dst + off) =
                    __halves2half2(__float2half_rn(v0), __float2half_rn(v1));
            }
        }
    }
}

// ---------------------------------------------------------------------------
// Proj GEMM: out = attn @ w_proj^T + bias
// ---------------------------------------------------------------------------
__global__ __launch_bounds__(128, 2) void gemm_proj_mma(const float* __restrict__ bias,
                                                        float* __restrict__ out) {
    extern __shared__ char smem[];
    const uint32_t sm32 = smem_u32(smem);
    const int m0 = blockIdx.y * BM;
    const int n0 = blockIdx.x * BN;

    float acc[4][8][4];
#pragma unroll
    for (int i = 0; i < 4; i++)
#pragma unroll
        for (int j = 0; j < 8; j++)
#pragma unroll
            for (int k = 0; k < 4; k++) acc[i][j][k] = 0.f;

    mma_mainloop(g_attn, g_wproj, m0, n0, sm32, acc);

    const int tid = threadIdx.x;
    const int lane = tid & 31;
    const int wid = tid >> 5;
    const int wm = wid & 1, wn = wid >> 1;
    const int r0 = lane >> 2;
    const int c0 = (lane & 3) * 2;

#pragma unroll
    for (int ma = 0; ma < 4; ma++) {
#pragma unroll
        for (int na = 0; na < 8; na++) {
            const int colg = n0 + wn * 64 + na * 8 + c0;
            const float b0 = bias[colg], b1 = bias[colg + 1];
#pragma unroll
            for (int hf = 0; hf < 2; hf++) {
                const int m = m0 + wm * 64 + ma * 16 + r0 + hf * 8;
                float2 o = make_float2(acc[ma][na][hf * 2 + 0] + b0,
                                       acc[ma][na][hf * 2 + 1] + b1);
                *(float2*)(out + (size_t)m * CDIM + colg) = o;
            }
        }
    }
}

// ---------------------------------------------------------------------------
// fp32 -> fp16 converts. which: 0 = x, 1 = w_qkv, 2 = w_proj
// ---------------------------------------------------------------------------
__global__ void conv16_kernel(const float* __restrict__ in, int which, int n) {
    __half* dst = (which == 0) ? g_x16 : (which == 1) ? g_wqkv : g_wproj;
    int i = (blockIdx.x * blockDim.x + threadIdx.x) * 4;
    if (i >= n) return;
    float4 v = *(const float4*)(in + i);
    *(__half2*)(dst + i)     = __halves2half2(__float2half_rn(v.x), __float2half_rn(v.y));
    *(__half2*)(dst + i + 2) = __halves2half2(__float2half_rn(v.z), __float2half_rn(v.w));
}

// ---------------------------------------------------------------------------
// kv via mma: per (bh, 1/16 split): kv[64d][64e] = k^T v; ksum side reduction.
// ---------------------------------------------------------------------------
__device__ __forceinline__ void kv_load_stage(uint32_t sb, size_t gbase, int tid) {
#pragma unroll
    for (int t = 0; t < 2; t++) {
        int u = t * 256 + tid;
        int row = u >> 3, cb = u & 7;
        uint32_t so = SWZ((uint32_t)(row * 128 + cb * 16));
        size_t g = gbase + (size_t)row * HD + cb * 8;
        cp16(sb + so, g_k16 + g);
        cp16(sb + 8192 + so, g_v + g);
    }
}

__global__ __launch_bounds__(256, 2) void kv_mma_kernel() {
    extern __shared__ char smem[];
    const uint32_t sm32 = smem_u32(smem);
    const int tid = threadIdx.x, lane = tid & 31, wid = tid >> 5;
    const int bh = blockIdx.x >> 4, sp = blockIdx.x & 15;
    const int wm = wid & 1, wn = wid >> 1;
    const size_t nbase = (size_t)bh * NTOK + sp * (NTOK / KVSPLIT);

    float acc[2][2][4];
#pragma unroll
    for (int i = 0; i < 2; i++)
#pragma unroll
        for (int j = 0; j < 2; j++)
#pragma unroll
            for (int k = 0; k < 4; k++) acc[i][j][k] = 0.f;
    float ksacc = 0.f;
    const int ks_d = tid & 63, ks_q = tid >> 6;

    kv_load_stage(sm32, nbase * HD, tid);
    CP_COMMIT();

    const int l7 = lane & 7, lg = lane >> 3;
    const int an_off = ((lg >> 1) ? 8 : 0) + l7;
    const int ad_off = (lg & 1) ? 8 : 0;
    const int bn_off = ((lg & 1) ? 8 : 0) + l7;
    const int be_off = (lg >> 1) ? 8 : 0;
    const int d0 = wm * 32;
    const int e0 = wn * 16;

    for (int c = 0; c < 4; c++) {
        CP_WAIT0();
        __syncthreads();
        if (c + 1 < 4) {
            kv_load_stage(sm32 + ((c + 1) & 1) * KV_STAGE,
                          (nbase + (c + 1) * 64) * HD, tid);
            CP_COMMIT();
        }
        const uint32_t sb = sm32 + (c & 1) * KV_STAGE;
#pragma unroll
        for (int kk = 0; kk < 64; kk += 16) {
            uint32_t ak[2][4], bv[4];
#pragma unroll
            for (int ma = 0; ma < 2; ma++) {
                uint32_t ad = SWZ((uint32_t)((kk + an_off) * 128 +
                                             (d0 + ma * 16 + ad_off) * 2));
                ldm4t(ak[ma], sb + ad);
            }
            uint32_t bd = SWZ((uint32_t)((kk + bn_off) * 128 + (e0 + be_off) * 2));
            ldm4t(bv, sb + 8192 + bd);
#pragma unroll
            for (int ma = 0; ma < 2; ma++)
#pragma unroll
                for (int nb = 0; nb < 2; nb++)
                    mma16816(acc[ma][nb], ak[ma], bv[nb * 2], bv[nb * 2 + 1]);
        }
#pragma unroll
        for (int nn = 0; nn < 16; nn++) {
            int n = ks_q * 16 + nn;
            uint32_t off = SWZ((uint32_t)(n * 128 + ks_d * 2));
            ksacc += __half2float(*(const __half*)(smem + (c & 1) * KV_STAGE + off));
        }
    }

    float* kssm = (float*)(smem + 2 * KV_STAGE);
    kssm[ks_q * 64 + ks_d] = ksacc;
    __syncthreads();
    if (tid < 64) {
        float s = kssm[tid] + kssm[64 + tid] + kssm[128 + tid] + kssm[192 + tid];
        g_ksum_part[(sp * NBH + bh) * HD + tid] = s;
    }

    const int r0 = lane >> 2, c0 = (lane & 3) * 2;
    float* kvout = g_kv_part + (size_t)(sp * NBH + bh) * (HD * HD);
#pragma unroll
    for (int ma = 0; ma < 2; ma++)
#pragma unroll
        for (int nb = 0; nb < 2; nb++)
#pragma unroll
            for (int hf = 0; hf < 2; hf++) {
                int d = d0 + ma * 16 + r0 + hf * 8;
                int e = e0 + nb * 8 + c0;
                *(float2*)(kvout + d * 64 + e) =
                    make_float2(acc[ma][nb][hf * 2], acc[ma][nb][hf * 2 + 1]);
            }
}

// ---------------------------------------------------------------------------
// kv reduce: sum partials, write kvT fp16 ([e][d]) + ksum fp32.
// ---------------------------------------------------------------------------
__global__ __launch_bounds__(256) void kv_reduce_kernel() {
    __shared__ float kvsm[64][65];
    const int bh = blockIdx.x;
    const int tid = threadIdx.x;
    for (int j = tid; j < HD * HD; j += 256) {
        float s = 0.f;
#pragma unroll
        for (int p = 0; p < KVSPLIT; p++)
            s += g_kv_part[(size_t)(p * NBH + bh) * (HD * HD) + j];
        kvsm[j >> 6][j & 63] = s;
    }
    if (tid < HD) {
        float s = 0.f;
#pragma unroll
        for (int p = 0; p < KVSPLIT; p++)
            s += g_ksum_part[(p * NBH + bh) * HD + tid];
        g_ksum[bh * HD + tid] = s;
    }
    __syncthreads();
    for (int j = tid; j < HD * HD; j += 256) {
        int e = j >> 6, d = j & 63;
        g_kvT[(size_t)bh * (HD * HD) + j] = __float2half_rn(kvsm[d][e]);
    }
}

// ---------------------------------------------------------------------------
// attn via mma: num = q @ kvT^T; /(q.ksum+eps); writes attn fp16.
// ---------------------------------------------------------------------------
__global__ __launch_bounds__(256, 2) void attn_mma_kernel() {
    extern __shared__ char smem[];
    const uint32_t sm32 = smem_u32(smem);
    const int tid = threadIdx.x, lane = tid & 31, wid = tid >> 5;
    const int bh = blockIdx.y;
    const int bb = bh >> 4, h = bh & 15;
    const int row0 = blockIdx.x * 128;
    const int wm = wid & 3, wn = wid >> 2;

    {
        size_t qbase = ((size_t)bh * NTOK + row0) * HD;
#pragma unroll
        for (int t = 0; t < 4; t++) {
            int u = t * 256 + tid;
            int row = u >> 3, cb = u & 7;
            uint32_t so = SWZ((uint32_t)(row * 128 + cb * 16));
            cp16(sm32 + AT_Q + so, g_q16 + qbase + (size_t)row * HD + cb * 8);
        }
#pragma unroll
        for (int t = 0; t < 2; t++) {
            int u = t * 256 + tid;
            int row = u >> 3, cb = u & 7;
            uint32_t so = SWZ((uint32_t)(row * 128 + cb * 16));
            cp16(sm32 + AT_KV + so,
                 g_kvT + (size_t)bh * (HD * HD) + (size_t)row * HD + cb * 8);
        }
        if (tid < 64) ((float*)(smem + AT_KSUM))[tid] = g_ksum[bh * HD + tid];
        CP_COMMIT();
        CP_WAIT0();
        __syncthreads();
    }

    {
        int row = tid >> 1, hh = tid & 1;
        float s = 0.f;
        const float* kss = (const float*)(smem + AT_KSUM);
#pragma unroll
        for (int dd = 0; dd < 32; dd++) {
            int d = hh * 32 + dd;
            uint32_t off = SWZ((uint32_t)(row * 128 + d * 2));
            s += __half2float(*(const __half*)(smem + AT_Q + off)) * kss[d];
        }
        s += __shfl_xor_sync(0xFFFFFFFFu, s, 1);
        if (hh == 0) ((float*)(smem + AT_INV))[row] = 1.f / (s + 1e-8f);
        __syncthreads();
    }

    float acc[2][4][4];
#pragma unroll
    for (int i = 0; i < 2; i++)
#pragma unroll
        for (int j = 0; j < 4; j++)
#pragma unroll
            for (int k = 0; k < 4; k++) acc[i][j][k] = 0.f;

    const int a_row = lane & 15;
    const int a_koff = (lane & 16) ? 8 : 0;
    const int b_row = (lane & 7) + ((lane & 16) >> 1);
    const int b_koff = (lane & 8) ? 8 : 0;

#pragma unroll
    for (int kk = 0; kk < 64; kk += 16) {
        uint32_t qa[2][4], kvb[2][4];
#pragma unroll
        for (int ma = 0; ma < 2; ma++) {
            uint32_t ad = SWZ((uint32_t)((wm * 32 + ma * 16 + a_row) * 128 +
                                         (kk + a_koff) * 2));
            ldm4(qa[ma], sm32 + AT_Q + ad);
        }
#pragma unroll
        for (int nb = 0; nb < 2; nb++) {
            uint32_t bd = SWZ((uint32_t)((wn * 32 + nb * 16 + b_row) * 128 +
                                         (kk + b_koff) * 2));
            ldm4(kvb[nb], sm32 + AT_KV + bd);
        }
#pragma unroll
        for (int ma = 0; ma < 2; ma++)
#pragma unroll
            for (int na = 0; na < 4; na++)
                mma16816(acc[ma][na], qa[ma],
                         kvb[na >> 1][(na & 1) * 2], kvb[na >> 1][(na & 1) * 2 + 1]);
    }

    const int r0 = lane >> 2, c0 = (lane & 3) * 2;
    const float* invp = (const float*)(smem + AT_INV);
#pragma unroll
    for (int ma = 0; ma < 2; ma++)
#pragma unroll
        for (int na = 0; na < 4; na++)
#pragma unroll
            for (int hf = 0; hf < 2; hf++) {
                int row = wm * 32 + ma * 16 + r0 + hf * 8;
                float iv = invp[row];
                int e = wn * 32 + na * 8 + c0;
                float v0 = acc[ma][na][hf * 2 + 0] * iv;
                float v1 = acc[ma][na][hf * 2 + 1] * iv;
                size_t ob = ((size_t)(bb * NTOK + row0 + row)) * CDIM + h * HD + e;
                *(__half2*)(g_attn + ob) =
                    __halves2half2(__float2half_rn(v0), __float2half_rn(v1));
            }
}

// ---------------------------------------------------------------------------
extern "C" void kernel_launch(void* const* d_in, const int* in_sizes, int n_in,
                              void* d_out, int out_size) {
    const float* x      = (const float*)d_in[0];
    const float* w_qkv  = (const float*)d_in[1];
    const float* w_proj = (const float*)d_in[2];
    const float* b_proj = (const float*)d_in[3];
    float* out = (float*)d_out;

    cudaFuncSetAttribute(gemm_qkv_mma, cudaFuncAttributeMaxDynamicSharedMemorySize,
                         SMEM_GEMM_BYTES);
    cudaFuncSetAttribute(gemm_proj_mma, cudaFuncAttributeMaxDynamicSharedMemorySize,
                         SMEM_GEMM_BYTES);
    cudaFuncSetAttribute(kv_mma_kernel, cudaFuncAttributeMaxDynamicSharedMemorySize,
                         SMEM_KV_BYTES);
    cudaFuncSetAttribute(attn_mma_kernel, cudaFuncAttributeMaxDynamicSharedMemorySize,
                         SMEM_AT_BYTES);

    conv16_kernel<<<(MTOT * KDIM) / 1024, 256>>>(x, 0, MTOT * KDIM);
    conv16_kernel<<<(NQKV * KDIM) / 1024, 256>>>(w_qkv, 1, NQKV * KDIM);
    conv16_kernel<<<(CDIM * KDIM) / 1024, 256>>>(w_proj, 2, CDIM * KDIM);

    gemm_qkv_mma<<<dim3(NQKV / BN, MTOT / BM), 128, SMEM_GEMM_BYTES>>>();

    kv_mma_kernel<<<NBH * KVSPLIT, 256, SMEM_KV_BYTES>>>();
    kv_reduce_kernel<<<NBH, 256>>>();

    attn_mma_kernel<<<dim3(NTOK / 128, NBH), 256, SMEM_AT_BYTES>>>();

    gemm_proj_mma<<<dim3(CDIM / BN, MTOT / BM), 128, SMEM_GEMM_BYTES>>>(b_proj, out);
}

// round 13
// speedup vs baseline: 1.0629x; 1.0629x over previous
#include <cuda_runtime.h>
#include <cuda_fp16.h>
#include <math.h>
#include <stdint.h>

#define NB    4
#define NTOK  4096
#define CDIM  1024
#define NH    16
#define HD    64
#define NBH   64
#define MTOT  16384
#define KDIM  1024
#define NQKV  3072

// GEMM tiling: single-pass fp16, 3-stage pipeline (R9 configuration)
#define BM 128
#define BN 128
#define BK 64
#define NCHUNK (KDIM / BK)      // 16
#define TILE_BYTES (128 * 128)              // 16384
#define OFF_A 0
#define OFF_B TILE_BYTES
#define STAGE_BYTES (2 * TILE_BYTES)        // 32768
#define NSTAGE 3
#define SMEM_GEMM_BYTES (NSTAGE * STAGE_BYTES)  // 98304

// SW128 swizzle
#define SWZ(o) ((o) ^ (((o) >> 3) & 0x70))

#define KVSPLIT 16
#define KV_STAGE 16384
#define SMEM_KV_BYTES (2 * KV_STAGE + 1024)   // 33792

// attn kernel smem offsets
#define AT_Q    0
#define AT_KV   16384
#define AT_KSUM 24576
#define AT_INV  24832
#define SMEM_AT_BYTES 25344

// fused convert sizes (in float4 units)
#define CVT_X_V4   ((MTOT * KDIM) / 4)      // 4194304
#define CVT_WQ_V4  ((NQKV * KDIM) / 4)      // 786432
#define CVT_WP_V4  ((CDIM * KDIM) / 4)      // 262144
#define CVT_TOT_V4 (CVT_X_V4 + CVT_WQ_V4 + CVT_WP_V4)

// ---------------------------------------------------------------------------
// Scratch (device globals)
// ---------------------------------------------------------------------------
__device__ __half g_x16[MTOT * KDIM];
__device__ __half g_wqkv[NQKV * KDIM];
__device__ __half g_wproj[CDIM * KDIM];
__device__ __half g_q16[NBH * NTOK * HD];
__device__ __half g_k16[NBH * NTOK * HD];
__device__ __half g_v[NBH * NTOK * HD];
__device__ float g_kv_part[KVSPLIT * NBH * HD * HD];
__device__ float g_ksum_part[KVSPLIT * NBH * HD];
__device__ float g_ksum[NBH * HD];
__device__ __half g_kvT[NBH * HD * HD];
__device__ __half g_attn[MTOT * CDIM];

__device__ __forceinline__ float elu1(float x) {
    return x > 0.f ? x + 1.f : expf(x);
}

// ---------------------------------------------------------------------------
// PTX helpers (compute_103-safe)
// ---------------------------------------------------------------------------
__device__ __forceinline__ uint32_t smem_u32(const void* p) {
    uint32_t a;
    asm("{ .reg .u64 t; cvta.to.shared.u64 t, %1; cvt.u32.u64 %0, t; }" : "=r"(a) : "l"(p));
    return a;
}
__device__ __forceinline__ void cp16(uint32_t s, const void* g) {
    asm volatile("cp.async.cg.shared.global [%0], [%1], 16;" :: "r"(s), "l"(g));
}
#define CP_COMMIT() asm volatile("cp.async.commit_group;" ::: "memory")
#define CP_WAIT1()  asm volatile("cp.async.wait_group 1;" ::: "memory")
#define CP_WAIT0()  asm volatile("cp.async.wait_group 0;" ::: "memory")

__device__ __forceinline__ void ldm4(uint32_t* r, uint32_t addr) {
    asm volatile("ldmatrix.sync.aligned.m8n8.x4.shared.b16 {%0,%1,%2,%3}, [%4];"
                 : "=r"(r[0]), "=r"(r[1]), "=r"(r[2]), "=r"(r[3]) : "r"(addr));
}
__device__ __forceinline__ void ldm4t(uint32_t* r, uint32_t addr) {
    asm volatile("ldmatrix.sync.aligned.m8n8.x4.trans.shared.b16 {%0,%1,%2,%3}, [%4];"
                 : "=r"(r[0]), "=r"(r[1]), "=r"(r[2]), "=r"(r[3]) : "r"(addr));
}
__device__ __forceinline__ void mma16816(float* d, const uint32_t* a,
                                         uint32_t b0, uint32_t b1) {
    asm volatile(
        "mma.sync.aligned.m16n8k16.row.col.f32.f16.f16.f32 "
        "{%0,%1,%2,%3}, {%4,%5,%6,%7}, {%8,%9}, {%0,%1,%2,%3};"
        : "+f"(d[0]), "+f"(d[1]), "+f"(d[2]), "+f"(d[3])
        : "r"(a[0]), "r"(a[1]), "r"(a[2]), "r"(a[3]), "r"(b0), "r"(b1));
}

// ---------------------------------------------------------------------------
// GEMM stage loader (A, B): 128x64 fp16 tiles, SW128 rows. 8 cp16/thread.
// ---------------------------------------------------------------------------
__device__ __forceinline__ void load_stage(
    uint32_t sbase,
    const __half* __restrict__ A, const __half* __restrict__ B,
    int m0, int n0, int kc, int tid)
{
#pragma unroll
    for (int t = 0; t < 4; t++) {
        int idx = t * 256 + tid;
        int row = idx >> 3;
        int c16 = idx & 7;
        uint32_t so = SWZ((uint32_t)(row * 128 + c16 * 16));
        cp16(sbase + OFF_A + so, A + (size_t)(m0 + row) * KDIM + kc + c16 * 8);
        cp16(sbase + OFF_B + so, B + (size_t)(n0 + row) * KDIM + kc + c16 * 8);
    }
}

// ---------------------------------------------------------------------------
// GEMM mainloop: acc[2][8][4] += A*B over K=1024. Single pass, 3-stage.
// (R9 configuration: 8 warps x 32x64 warp tile, 256 threads, 2 CTA/SM.)
// ---------------------------------------------------------------------------
__device__ __forceinline__ void mma_mainloop(
    const __half* __restrict__ A, const __half* __restrict__ B,
    int m0, int n0, uint32_t sm32, float acc[2][8][4])
{
    const int tid = threadIdx.x;
    const int lane = tid & 31;
    const int wid = tid >> 5;
    const int wm = wid & 3;
    const int wn = wid >> 2;

    load_stage(sm32, A, B, m0, n0, 0, tid);
    CP_COMMIT();
    load_stage(sm32 + STAGE_BYTES, A, B, m0, n0, BK, tid);
    CP_COMMIT();

    const int a_row = (lane & 15);
    const int a_koff = (lane & 16) ? 8 : 0;
    const int b_row = (lane & 7) + ((lane & 16) >> 1);
    const int b_koff = (lane & 8) ? 8 : 0;

    const uint32_t aoff0 = (uint32_t)((wm * 32 + a_row) * 128 + a_koff * 2);
    const uint32_t aoff1 = aoff0 + 16 * 128;
    uint32_t boffs[4];
#pragma unroll
    for (int nb = 0; nb < 4; nb++)
        boffs[nb] = (uint32_t)((wn * 64 + nb * 16 + b_row) * 128 + b_koff * 2);

    int cur = 0, pre = 2;
    for (int c = 0; c < NCHUNK; c++) {
        if (c == NCHUNK - 1) CP_WAIT0(); else CP_WAIT1();
        __syncthreads();

        if (c + 2 < NCHUNK) {
            load_stage(sm32 + pre * STAGE_BYTES, A, B, m0, n0, (c + 2) * BK, tid);
            CP_COMMIT();
        }

        const uint32_t sb = sm32 + cur * STAGE_BYTES;
#pragma unroll
        for (int kk = 0; kk < BK; kk += 16) {
            uint32_t aa[2][4], bb[4][4];
            const uint32_t kb = (uint32_t)(kk * 2);
            ldm4(aa[0], sb + OFF_A + SWZ(aoff0 + kb));
            ldm4(aa[1], sb + OFF_A + SWZ(aoff1 + kb));
#pragma unroll
            for (int nb = 0; nb < 4; nb++)
                ldm4(bb[nb], sb + OFF_B + SWZ(boffs[nb] + kb));
#pragma unroll
            for (int ma = 0; ma < 2; ma++)
#pragma unroll
                for (int na = 0; na < 8; na++)
                    mma16816(acc[ma][na], aa[ma],
                             bb[na >> 1][(na & 1) * 2], bb[na >> 1][(na & 1) * 2 + 1]);
        }
        cur = (cur == NSTAGE - 1) ? 0 : cur + 1;
        pre = (pre == NSTAGE - 1) ? 0 : pre + 1;
    }
}

// ---------------------------------------------------------------------------
// QKV GEMM: epilogue applies elu+1 to q,k; writes q,k,v single fp16.
// ---------------------------------------------------------------------------
__global__ __launch_bounds__(256, 2) void gemm_qkv_mma() {
    extern __shared__ char smem[];
    const uint32_t sm32 = smem_u32(smem);
    const int m0 = blockIdx.y * BM;
    const int n0 = blockIdx.x * BN;

    float acc[2][8][4];
#pragma unroll
    for (int i = 0; i < 2; i++)
#pragma unroll
        for (int j = 0; j < 8; j++)
#pragma unroll
            for (int k = 0; k < 4; k++) acc[i][j][k] = 0.f;

    mma_mainloop(g_x16, g_wqkv, m0, n0, sm32, acc);

    const int tid = threadIdx.x;
    const int lane = tid & 31;
    const int wid = tid >> 5;
    const int wm = wid & 3, wn = wid >> 2;
    const int r0 = lane >> 2;
    const int c0 = (lane & 3) * 2;

#pragma unroll
    for (int ma = 0; ma < 2; ma++) {
#pragma unroll
        for (int na = 0; na < 8; na++) {
            const int colg = n0 + wn * 64 + na * 8 + c0;
            const int part = colg >> 10;
            const int h = (colg & 1023) >> 6;
            const int d = colg & 63;
            __half* dst = (part == 0) ? g_q16 : (part == 1) ? g_k16 : g_v;
            const bool feat = part < 2;
#pragma unroll
            for (int hf = 0; hf < 2; hf++) {
                const int m = m0 + wm * 32 + ma * 16 + r0 + hf * 8;
                const int bb = m >> 12, t = m & 4095;
                float v0 = acc[ma][na][hf * 2 + 0];
                float v1 = acc[ma][na][hf * 2 + 1];
                if (feat) { v0 = elu1(v0); v1 = elu1(v1); }
                size_t off = ((size_t)(bb * NH + h) * NTOK + t) * HD + d;
                *(__half2*)(dst + off) =
                    __halves2half2(__float2half_rn(v0), __float2half_rn(v1));
            }
        }
    }
}

// ---------------------------------------------------------------------------
// Proj GEMM: out = attn @ w_proj^T + bias
// ---------------------------------------------------------------------------
__global__ __launch_bounds__(256, 2) void gemm_proj_mma(const float* __restrict__ bias,
                                                        float* __restrict__ out) {
    extern __shared__ char smem[];
    const uint32_t sm32 = smem_u32(smem);
    const int m0 = blockIdx.y * BM;
    const int n0 = blockIdx.x * BN;

    float acc[2][8][4];
#pragma unroll
    for (int i = 0; i < 2; i++)
#pragma unroll
        for (int j = 0; j < 8; j++)
#pragma unroll
            for (int k = 0; k < 4; k++) acc[i][j][k] = 0.f;

    mma_mainloop(g_attn, g_wproj, m0, n0, sm32, acc);

    const int tid = threadIdx.x;
    const int lane = tid & 31;
    const int wid = tid >> 5;
    const int wm = wid & 3, wn = wid >> 2;
    const int r0 = lane >> 2;
    const int c0 = (lane & 3) * 2;

#pragma unroll
    for (int ma = 0; ma < 2; ma++) {
#pragma unroll
        for (int na = 0; na < 8; na++) {
            const int colg = n0 + wn * 64 + na * 8 + c0;
            const float b0 = bias[colg], b1 = bias[colg + 1];
#pragma unroll
            for (int hf = 0; hf < 2; hf++) {
                const int m = m0 + wm * 32 + ma * 16 + r0 + hf * 8;
                float2 o = make_float2(acc[ma][na][hf * 2 + 0] + b0,
                                       acc[ma][na][hf * 2 + 1] + b1);
                *(float2*)(out + (size_t)m * CDIM + colg) = o;
            }
        }
    }
}

// ---------------------------------------------------------------------------
// Fused fp32 -> fp16 convert for x, w_qkv, w_proj in ONE launch.
// Index space is float4 units over the concatenation [x | w_qkv | w_proj].
// ---------------------------------------------------------------------------
__global__ void conv16_fused_kernel(const float* __restrict__ x,
                                    const float* __restrict__ wq,
                                    const float* __restrict__ wp) {
    int i4 = blockIdx.x * blockDim.x + threadIdx.x;
    if (i4 >= CVT_TOT_V4) return;
    const float* src;
    __half* dst;
    int off4;
    if (i4 < CVT_X_V4) {
        src = x; dst = g_x16; off4 = i4;
    } else if (i4 < CVT_X_V4 + CVT_WQ_V4) {
        src = wq; dst = g_wqkv; off4 = i4 - CVT_X_V4;
    } else {
        src = wp; dst = g_wproj; off4 = i4 - CVT_X_V4 - CVT_WQ_V4;
    }
    int i = off4 * 4;
    float4 v = *(const float4*)(src + i);
    *(__half2*)(dst + i)     = __halves2half2(__float2half_rn(v.x), __float2half_rn(v.y));
    *(__half2*)(dst + i + 2) = __halves2half2(__float2half_rn(v.z), __float2half_rn(v.w));
}

// ---------------------------------------------------------------------------
// kv via mma: per (bh, 1/16 split): kv[64d][64e] = k^T v; ksum side reduction.
// ---------------------------------------------------------------------------
__device__ __forceinline__ void kv_load_stage(uint32_t sb, size_t gbase, int tid) {
#pragma unroll
    for (int t = 0; t < 2; t++) {
        int u = t * 256 + tid;
        int row = u >> 3, cb = u & 7;
        uint32_t so = SWZ((uint32_t)(row * 128 + cb * 16));
        size_t g = gbase + (size_t)row * HD + cb * 8;
        cp16(sb + so, g_k16 + g);
        cp16(sb + 8192 + so, g_v + g);
    }
}

__global__ __launch_bounds__(256, 2) void kv_mma_kernel() {
    extern __shared__ char smem[];
    const uint32_t sm32 = smem_u32(smem);
    const int tid = threadIdx.x, lane = tid & 31, wid = tid >> 5;
    const int bh = blockIdx.x >> 4, sp = blockIdx.x & 15;
    const int wm = wid & 1, wn = wid >> 1;
    const size_t nbase = (size_t)bh * NTOK + sp * (NTOK / KVSPLIT);

    float acc[2][2][4];
#pragma unroll
    for (int i = 0; i < 2; i++)
#pragma unroll
        for (int j = 0; j < 2; j++)
#pragma unroll
            for (int k = 0; k < 4; k++) acc[i][j][k] = 0.f;
    float ksacc = 0.f;
    const int ks_d = tid & 63, ks_q = tid >> 6;

    kv_load_stage(sm32, nbase * HD, tid);
    CP_COMMIT();

    const int l7 = lane & 7, lg = lane >> 3;
    const int an_off = ((lg >> 1) ? 8 : 0) + l7;
    const int ad_off = (lg & 1) ? 8 : 0;
    const int bn_off = ((lg & 1) ? 8 : 0) + l7;
    const int be_off = (lg >> 1) ? 8 : 0;
    const int d0 = wm * 32;
    const int e0 = wn * 16;

    for (int c = 0; c < 4; c++) {
        CP_WAIT0();
        __syncthreads();
        if (c + 1 < 4) {
            kv_load_stage(sm32 + ((c + 1) & 1) * KV_STAGE,
                          (nbase + (c + 1) * 64) * HD, tid);
            CP_COMMIT();
        }
        const uint32_t sb = sm32 + (c & 1) * KV_STAGE;
#pragma unroll
        for (int kk = 0; kk < 64; kk += 16) {
            uint32_t ak[2][4], bv[4];
#pragma unroll
            for (int ma = 0; ma < 2; ma++) {
                uint32_t ad = SWZ((uint32_t)((kk + an_off) * 128 +
                                             (d0 + ma * 16 + ad_off) * 2));
                ldm4t(ak[ma], sb + ad);
            }
            uint32_t bd = SWZ((uint32_t)((kk + bn_off) * 128 + (e0 + be_off) * 2));
            ldm4t(bv, sb + 8192 + bd);
#pragma unroll
            for (int ma = 0; ma < 2; ma++)
#pragma unroll
                for (int nb = 0; nb < 2; nb++)
                    mma16816(acc[ma][nb], ak[ma], bv[nb * 2], bv[nb * 2 + 1]);
        }
#pragma unroll
        for (int nn = 0; nn < 16; nn++) {
            int n = ks_q * 16 + nn;
            uint32_t off = SWZ((uint32_t)(n * 128 + ks_d * 2));
            ksacc += __half2float(*(const __half*)(smem + (c & 1) * KV_STAGE + off));
        }
    }

    float* kssm = (float*)(smem + 2 * KV_STAGE);
    kssm[ks_q * 64 + ks_d] = ksacc;
    __syncthreads();
    if (tid < 64) {
        float s = kssm[tid] + kssm[64 + tid] + kssm[128 + tid] + kssm[192 + tid];
        g_ksum_part[(sp * NBH + bh) * HD + tid] = s;
    }

    const int r0 = lane >> 2, c0 = (lane & 3) * 2;
    float* kvout = g_kv_part + (size_t)(sp * NBH + bh) * (HD * HD);
#pragma unroll
    for (int ma = 0; ma < 2; ma++)
#pragma unroll
        for (int nb = 0; nb < 2; nb++)
#pragma unroll
            for (int hf = 0; hf < 2; hf++) {
                int d = d0 + ma * 16 + r0 + hf * 8;
                int e = e0 + nb * 8 + c0;
                *(float2*)(kvout + d * 64 + e) =
                    make_float2(acc[ma][nb][hf * 2], acc[ma][nb][hf * 2 + 1]);
            }
}

// ---------------------------------------------------------------------------
// kv reduce: 4 blocks per bh; each reduces a quarter of kv (1024 elements).
// Quarter 0 also reduces ksum. Writes kvT fp16 ([e][d]) + ksum fp32.
// ---------------------------------------------------------------------------
__global__ __launch_bounds__(256) void kv_reduce_kernel() {
    const int bh = blockIdx.x >> 2;
    const int qr = blockIdx.x & 3;
    const int tid = threadIdx.x;
    const int jbase = qr * 1024;

    __shared__ float kvsm[16][65];   // 16 d-rows x 64 e-cols per pass

    // quarter covers e in [qr*16, qr*16+16) for the transposed output:
    // process j = d*64+e with d full range, e in 16-col band? Simpler:
    // each quarter handles 1024 consecutive j of the [d][e] source,
    // i.e. d in [qr*16, qr*16+16), e full 64. Output kvT[e][d] scatter.
    for (int jj = tid; jj < 1024; jj += 256) {
        int j = jbase + jj;               // j = d*64 + e, d in quarter band
        float s = 0.f;
#pragma unroll
        for (int p = 0; p < KVSPLIT; p++)
            s += g_kv_part[(size_t)(p * NBH + bh) * (HD * HD) + j];
        kvsm[jj >> 6][jj & 63] = s;       // [d - qr*16][e]
    }
    if (qr == 0 && tid < HD) {
        float s = 0.f;
#pragma unroll
        for (int p = 0; p < KVSPLIT; p++)
            s += g_ksum_part[(p * NBH + bh) * HD + tid];
        g_ksum[bh * HD + tid] = s;
    }
    __syncthreads();
    // write transposed: kvT[e][d] for d in band, e in [0,64)
    for (int jj = tid; jj < 1024; jj += 256) {
        int dl = jj >> 6;                 // local d
        int e = jj & 63;
        int d = jbase / 64 + dl;
        g_kvT[(size_t)bh * (HD * HD) + e * HD + d] = __float2half_rn(kvsm[dl][e]);
    }
}

// ---------------------------------------------------------------------------
// attn via mma: num = q @ kvT^T; /(q.ksum+eps); writes attn fp16.
// ---------------------------------------------------------------------------
__global__ __launch_bounds__(256, 2) void attn_mma_kernel() {
    extern __shared__ char smem[];
    const uint32_t sm32 = smem_u32(smem);
    const int tid = threadIdx.x, lane = tid & 31, wid = tid >> 5;
    const int bh = blockIdx.y;
    const int bb = bh >> 4, h = bh & 15;
    const int row0 = blockIdx.x * 128;
    const int wm = wid & 3, wn = wid >> 2;

    {
        size_t qbase = ((size_t)bh * NTOK + row0) * HD;
#pragma unroll
        for (int t = 0; t < 4; t++) {
            int u = t * 256 + tid;
            int row = u >> 3, cb = u & 7;
            uint32_t so = SWZ((uint32_t)(row * 128 + cb * 16));
            cp16(sm32 + AT_Q + so, g_q16 + qbase + (size_t)row * HD + cb * 8);
        }
#pragma unroll
        for (int t = 0; t < 2; t++) {
            int u = t * 256 + tid;
            int row = u >> 3, cb = u & 7;
            uint32_t so = SWZ((uint32_t)(row * 128 + cb * 16));
            cp16(sm32 + AT_KV + so,
                 g_kvT + (size_t)bh * (HD * HD) + (size_t)row * HD + cb * 8);
        }
        if (tid < 64) ((float*)(smem + AT_KSUM))[tid] = g_ksum[bh * HD + tid];
        CP_COMMIT();
        CP_WAIT0();
        __syncthreads();
    }

    {
        int row = tid >> 1, hh = tid & 1;
        float s = 0.f;
        const float* kss = (const float*)(smem + AT_KSUM);
#pragma unroll
        for (int dd = 0; dd < 32; dd++) {
            int d = hh * 32 + dd;
            uint32_t off = SWZ((uint32_t)(row * 128 + d * 2));
            s += __half2float(*(const __half*)(smem + AT_Q + off)) * kss[d];
        }
        s += __shfl_xor_sync(0xFFFFFFFFu, s, 1);
        if (hh == 0) ((float*)(smem + AT_INV))[row] = 1.f / (s + 1e-8f);
        __syncthreads();
    }

    float acc[2][4][4];
#pragma unroll
    for (int i = 0; i < 2; i++)
#pragma unroll
        for (int j = 0; j < 4; j++)
#pragma unroll
            for (int k = 0; k < 4; k++) acc[i][j][k] = 0.f;

    const int a_row = lane & 15;
    const int a_koff = (lane & 16) ? 8 : 0;
    const int b_row = (lane & 7) + ((lane & 16) >> 1);
    const int b_koff = (lane & 8) ? 8 : 0;

#pragma unroll
    for (int kk = 0; kk < 64; kk += 16) {
        uint32_t qa[2][4], kvb[2][4];
#pragma unroll
        for (int ma = 0; ma < 2; ma++) {
            uint32_t ad = SWZ((uint32_t)((wm * 32 + ma * 16 + a_row) * 128 +
                                         (kk + a_koff) * 2));
            ldm4(qa[ma], sm32 + AT_Q + ad);
        }
#pragma unroll
        for (int nb = 0; nb < 2; nb++) {
            uint32_t bd = SWZ((uint32_t)((wn * 32 + nb * 16 + b_row) * 128 +
                                         (kk + b_koff) * 2));
            ldm4(kvb[nb], sm32 + AT_KV + bd);
        }
#pragma unroll
        for (int ma = 0; ma < 2; ma++)
#pragma unroll
            for (int na = 0; na < 4; na++)
                mma16816(acc[ma][na], qa[ma],
                         kvb[na >> 1][(na & 1) * 2], kvb[na >> 1][(na & 1) * 2 + 1]);
    }

    const int r0 = lane >> 2, c0 = (lane & 3) * 2;
    const float* invp = (const float*)(smem + AT_INV);
#pragma unroll
    for (int ma = 0; ma < 2; ma++)
#pragma unroll
        for (int na = 0; na < 4; na++)
#pragma unroll
            for (int hf = 0; hf < 2; hf++) {
                int row = wm * 32 + ma * 16 + r0 + hf * 8;
                float iv = invp[row];
                int e = wn * 32 + na * 8 + c0;
                float v0 = acc[ma][na][hf * 2 + 0] * iv;
                float v1 = acc[ma][na][hf * 2 + 1] * iv;
                size_t ob = ((size_t)(bb * NTOK + row0 + row)) * CDIM + h * HD + e;
                *(__half2*)(g_attn + ob) =
                    __halves2half2(__float2half_rn(v0), __float2half_rn(v1));
            }
}

// ---------------------------------------------------------------------------
extern "C" void kernel_launch(void* const* d_in, const int* in_sizes, int n_in,
                              void* d_out, int out_size) {
    const float* x      = (const float*)d_in[0];
    const float* w_qkv  = (const float*)d_in[1];
    const float* w_proj = (const float*)d_in[2];
    const float* b_proj = (const float*)d_in[3];
    float* out = (float*)d_out;

    cudaFuncSetAttribute(gemm_qkv_mma, cudaFuncAttributeMaxDynamicSharedMemorySize,
                         SMEM_GEMM_BYTES);
    cudaFuncSetAttribute(gemm_proj_mma, cudaFuncAttributeMaxDynamicSharedMemorySize,
                         SMEM_GEMM_BYTES);
    cudaFuncSetAttribute(kv_mma_kernel, cudaFuncAttributeMaxDynamicSharedMemorySize,
                         SMEM_KV_BYTES);
    cudaFuncSetAttribute(attn_mma_kernel, cudaFuncAttributeMaxDynamicSharedMemorySize,
                         SMEM_AT_BYTES);

    conv16_fused_kernel<<<(CVT_TOT_V4 + 255) / 256, 256>>>(x, w_qkv, w_proj);

    gemm_qkv_mma<<<dim3(NQKV / BN, MTOT / BM), 256, SMEM_GEMM_BYTES>>>();

    kv_mma_kernel<<<NBH * KVSPLIT, 256, SMEM_KV_BYTES>>>();
    kv_reduce_kernel<<<NBH * 4, 256>>>();

    attn_mma_kernel<<<dim3(NTOK / 128, NBH), 256, SMEM_AT_BYTES>>>();

    gemm_proj_mma<<<dim3(CDIM / BN, MTOT / BM), 256, SMEM_GEMM_BYTES>>>(b_proj, out);
}

// round 14
// speedup vs baseline: 1.0644x; 1.0014x over previous
#include <cuda_runtime.h>
#include <cuda_fp16.h>
#include <math.h>
#include <stdint.h>

#define NB    4
#define NTOK  4096
#define CDIM  1024
#define NH    16
#define HD    64
#define NBH   64
#define MTOT  16384
#define KDIM  1024
#define NQKV  3072

// GEMM tiling: single-pass fp16, 3-stage pipeline (R9 configuration)
#define BM 128
#define BN 128
#define BK 64
#define NCHUNK (KDIM / BK)      // 16
#define TILE_BYTES (128 * 128)              // 16384
#define OFF_A 0
#define OFF_B TILE_BYTES
#define STAGE_BYTES (2 * TILE_BYTES)        // 32768
#define NSTAGE 3
#define SMEM_GEMM_BYTES (NSTAGE * STAGE_BYTES)  // 98304

// SW128 swizzle
#define SWZ(o) ((o) ^ (((o) >> 3) & 0x70))

#define KVSPLIT 16
#define KV_STAGE 16384
#define SMEM_KV_BYTES (2 * KV_STAGE + 1024)   // 33792

// attn kernel smem offsets
#define AT_Q    0
#define AT_KV   16384
#define AT_KSUM 24576
#define AT_INV  24832
#define SMEM_AT_BYTES 25344

// fused convert sizes (in float4 units)
#define CVT_X_V4   ((MTOT * KDIM) / 4)
#define CVT_WQ_V4  ((NQKV * KDIM) / 4)
#define CVT_WP_V4  ((CDIM * KDIM) / 4)
#define CVT_TOT_V4 (CVT_X_V4 + CVT_WQ_V4 + CVT_WP_V4)

// ---------------------------------------------------------------------------
// Scratch (device globals)
// ---------------------------------------------------------------------------
__device__ __half g_x16[MTOT * KDIM];
__device__ __half g_wqkv[NQKV * KDIM];
__device__ __half g_wproj[CDIM * KDIM];
__device__ __half g_q16[NBH * NTOK * HD];
__device__ __half g_k16[NBH * NTOK * HD];
__device__ __half g_v[NBH * NTOK * HD];
__device__ __half g_kv_part[KVSPLIT * NBH * HD * HD];   // fp16 partials (8 MB)
__device__ float g_ksum_part[KVSPLIT * NBH * HD];
__device__ float g_ksum[NBH * HD];
__device__ __half g_kvT[NBH * HD * HD];
__device__ __half g_attn[MTOT * CDIM];

__device__ __forceinline__ float elu1(float x) {
    return x > 0.f ? x + 1.f : expf(x);
}

// ---------------------------------------------------------------------------
// PTX helpers (compute_103-safe)
// ---------------------------------------------------------------------------
__device__ __forceinline__ uint32_t smem_u32(const void* p) {
    uint32_t a;
    asm("{ .reg .u64 t; cvta.to.shared.u64 t, %1; cvt.u32.u64 %0, t; }" : "=r"(a) : "l"(p));
    return a;
}
__device__ __forceinline__ void cp16(uint32_t s, const void* g) {
    asm volatile("cp.async.cg.shared.global [%0], [%1], 16;" :: "r"(s), "l"(g));
}
#define CP_COMMIT() asm volatile("cp.async.commit_group;" ::: "memory")
#define CP_WAIT1()  asm volatile("cp.async.wait_group 1;" ::: "memory")
#define CP_WAIT0()  asm volatile("cp.async.wait_group 0;" ::: "memory")

__device__ __forceinline__ void ldm4(uint32_t* r, uint32_t addr) {
    asm volatile("ldmatrix.sync.aligned.m8n8.x4.shared.b16 {%0,%1,%2,%3}, [%4];"
                 : "=r"(r[0]), "=r"(r[1]), "=r"(r[2]), "=r"(r[3]) : "r"(addr));
}
__device__ __forceinline__ void ldm4t(uint32_t* r, uint32_t addr) {
    asm volatile("ldmatrix.sync.aligned.m8n8.x4.trans.shared.b16 {%0,%1,%2,%3}, [%4];"
                 : "=r"(r[0]), "=r"(r[1]), "=r"(r[2]), "=r"(r[3]) : "r"(addr));
}
__device__ __forceinline__ void mma16816(float* d, const uint32_t* a,
                                         uint32_t b0, uint32_t b1) {
    asm volatile(
        "mma.sync.aligned.m16n8k16.row.col.f32.f16.f16.f32 "
        "{%0,%1,%2,%3}, {%4,%5,%6,%7}, {%8,%9}, {%0,%1,%2,%3};"
        : "+f"(d[0]), "+f"(d[1]), "+f"(d[2]), "+f"(d[3])
        : "r"(a[0]), "r"(a[1]), "r"(a[2]), "r"(a[3]), "r"(b0), "r"(b1));
}

// ---------------------------------------------------------------------------
// GEMM stage loader (A, B): 128x64 fp16 tiles, SW128 rows. 8 cp16/thread.
// ---------------------------------------------------------------------------
__device__ __forceinline__ void load_stage(
    uint32_t sbase,
    const __half* __restrict__ A, const __half* __restrict__ B,
    int m0, int n0, int kc, int tid)
{
#pragma unroll
    for (int t = 0; t < 4; t++) {
        int idx = t * 256 + tid;
        int row = idx >> 3;
        int c16 = idx & 7;
        uint32_t so = SWZ((uint32_t)(row * 128 + c16 * 16));
        cp16(sbase + OFF_A + so, A + (size_t)(m0 + row) * KDIM + kc + c16 * 8);
        cp16(sbase + OFF_B + so, B + (size_t)(n0 + row) * KDIM + kc + c16 * 8);
    }
}

// ---------------------------------------------------------------------------
// GEMM mainloop: acc[2][8][4] += A*B over K=1024. Single pass, 3-stage.
// (R9 configuration: 8 warps x 32x64 warp tile, 256 threads, 2 CTA/SM.)
// ---------------------------------------------------------------------------
__device__ __forceinline__ void mma_mainloop(
    const __half* __restrict__ A, const __half* __restrict__ B,
    int m0, int n0, uint32_t sm32, float acc[2][8][4])
{
    const int tid = threadIdx.x;
    const int lane = tid & 31;
    const int wid = tid >> 5;
    const int wm = wid & 3;
    const int wn = wid >> 2;

    load_stage(sm32, A, B, m0, n0, 0, tid);
    CP_COMMIT();
    load_stage(sm32 + STAGE_BYTES, A, B, m0, n0, BK, tid);
    CP_COMMIT();

    const int a_row = (lane & 15);
    const int a_koff = (lane & 16) ? 8 : 0;
    const int b_row = (lane & 7) + ((lane & 16) >> 1);
    const int b_koff = (lane & 8) ? 8 : 0;

    const uint32_t aoff0 = (uint32_t)((wm * 32 + a_row) * 128 + a_koff * 2);
    const uint32_t aoff1 = aoff0 + 16 * 128;
    uint32_t boffs[4];
#pragma unroll
    for (int nb = 0; nb < 4; nb++)
        boffs[nb] = (uint32_t)((wn * 64 + nb * 16 + b_row) * 128 + b_koff * 2);

    int cur = 0, pre = 2;
    for (int c = 0; c < NCHUNK; c++) {
        if (c == NCHUNK - 1) CP_WAIT0(); else CP_WAIT1();
        __syncthreads();

        if (c + 2 < NCHUNK) {
            load_stage(sm32 + pre * STAGE_BYTES, A, B, m0, n0, (c + 2) * BK, tid);
            CP_COMMIT();
        }

        const uint32_t sb = sm32 + cur * STAGE_BYTES;
#pragma unroll
        for (int kk = 0; kk < BK; kk += 16) {
            uint32_t aa[2][4], bb[4][4];
            const uint32_t kb = (uint32_t)(kk * 2);
            ldm4(aa[0], sb + OFF_A + SWZ(aoff0 + kb));
            ldm4(aa[1], sb + OFF_A + SWZ(aoff1 + kb));
#pragma unroll
            for (int nb = 0; nb < 4; nb++)
                ldm4(bb[nb], sb + OFF_B + SWZ(boffs[nb] + kb));
#pragma unroll
            for (int ma = 0; ma < 2; ma++)
#pragma unroll
                for (int na = 0; na < 8; na++)
                    mma16816(acc[ma][na], aa[ma],
                             bb[na >> 1][(na & 1) * 2], bb[na >> 1][(na & 1) * 2 + 1]);
        }
        cur = (cur == NSTAGE - 1) ? 0 : cur + 1;
        pre = (pre == NSTAGE - 1) ? 0 : pre + 1;
    }
}

// ---------------------------------------------------------------------------
// QKV GEMM: epilogue applies elu+1 to q,k; writes q,k,v single fp16.
// ---------------------------------------------------------------------------
__global__ __launch_bounds__(256, 2) void gemm_qkv_mma() {
    extern __shared__ char smem[];
    const uint32_t sm32 = smem_u32(smem);
    const int m0 = blockIdx.y * BM;
    const int n0 = blockIdx.x * BN;

    float acc[2][8][4];
#pragma unroll
    for (int i = 0; i < 2; i++)
#pragma unroll
        for (int j = 0; j < 8; j++)
#pragma unroll
            for (int k = 0; k < 4; k++) acc[i][j][k] = 0.f;

    mma_mainloop(g_x16, g_wqkv, m0, n0, sm32, acc);

    const int tid = threadIdx.x;
    const int lane = tid & 31;
    const int wid = tid >> 5;
    const int wm = wid & 3, wn = wid >> 2;
    const int r0 = lane >> 2;
    const int c0 = (lane & 3) * 2;

#pragma unroll
    for (int ma = 0; ma < 2; ma++) {
#pragma unroll
        for (int na = 0; na < 8; na++) {
            const int colg = n0 + wn * 64 + na * 8 + c0;
            const int part = colg >> 10;
            const int h = (colg & 1023) >> 6;
            const int d = colg & 63;
            __half* dst = (part == 0) ? g_q16 : (part == 1) ? g_k16 : g_v;
            const bool feat = part < 2;
#pragma unroll
            for (int hf = 0; hf < 2; hf++) {
                const int m = m0 + wm * 32 + ma * 16 + r0 + hf * 8;
                const int bb = m >> 12, t = m & 4095;
                float v0 = acc[ma][na][hf * 2 + 0];
                float v1 = acc[ma][na][hf * 2 + 1];
                if (feat) { v0 = elu1(v0); v1 = elu1(v1); }
                size_t off = ((size_t)(bb * NH + h) * NTOK + t) * HD + d;
                *(__half2*)(dst + off) =
                    __halves2half2(__float2half_rn(v0), __float2half_rn(v1));
            }
        }
    }
}

// ---------------------------------------------------------------------------
// Proj GEMM: out = attn @ w_proj^T + bias
// ---------------------------------------------------------------------------
__global__ __launch_bounds__(256, 2) void gemm_proj_mma(const float* __restrict__ bias,
                                                        float* __restrict__ out) {
    extern __shared__ char smem[];
    const uint32_t sm32 = smem_u32(smem);
    const int m0 = blockIdx.y * BM;
    const int n0 = blockIdx.x * BN;

    float acc[2][8][4];
#pragma unroll
    for (int i = 0; i < 2; i++)
#pragma unroll
        for (int j = 0; j < 8; j++)
#pragma unroll
            for (int k = 0; k < 4; k++) acc[i][j][k] = 0.f;

    mma_mainloop(g_attn, g_wproj, m0, n0, sm32, acc);

    const int tid = threadIdx.x;
    const int lane = tid & 31;
    const int wid = tid >> 5;
    const int wm = wid & 3, wn = wid >> 2;
    const int r0 = lane >> 2;
    const int c0 = (lane & 3) * 2;

#pragma unroll
    for (int ma = 0; ma < 2; ma++) {
#pragma unroll
        for (int na = 0; na < 8; na++) {
            const int colg = n0 + wn * 64 + na * 8 + c0;
            const float b0 = bias[colg], b1 = bias[colg + 1];
#pragma unroll
            for (int hf = 0; hf < 2; hf++) {
                const int m = m0 + wm * 32 + ma * 16 + r0 + hf * 8;
                float2 o = make_float2(acc[ma][na][hf * 2 + 0] + b0,
                                       acc[ma][na][hf * 2 + 1] + b1);
                *(float2*)(out + (size_t)m * CDIM + colg) = o;
            }
        }
    }
}

// ---------------------------------------------------------------------------
// Fused fp32 -> fp16 convert for x, w_qkv, w_proj in ONE launch.
// ---------------------------------------------------------------------------
__global__ void conv16_fused_kernel(const float* __restrict__ x,
                                    const float* __restrict__ wq,
                                    const float* __restrict__ wp) {
    int i4 = blockIdx.x * blockDim.x + threadIdx.x;
    if (i4 >= CVT_TOT_V4) return;
    const float* src;
    __half* dst;
    int off4;
    if (i4 < CVT_X_V4) {
        src = x; dst = g_x16; off4 = i4;
    } else if (i4 < CVT_X_V4 + CVT_WQ_V4) {
        src = wq; dst = g_wqkv; off4 = i4 - CVT_X_V4;
    } else {
        src = wp; dst = g_wproj; off4 = i4 - CVT_X_V4 - CVT_WQ_V4;
    }
    int i = off4 * 4;
    float4 v = *(const float4*)(src + i);
    *(__half2*)(dst + i)     = __halves2half2(__float2half_rn(v.x), __float2half_rn(v.y));
    *(__half2*)(dst + i + 2) = __halves2half2(__float2half_rn(v.z), __float2half_rn(v.w));
}

// ---------------------------------------------------------------------------
// kv via mma: per (bh, 1/16 split): kv[64d][64e] = k^T v; ksum side reduction.
// Partials stored fp16.
// ---------------------------------------------------------------------------
__device__ __forceinline__ void kv_load_stage(uint32_t sb, size_t gbase, int tid) {
#pragma unroll
    for (int t = 0; t < 2; t++) {
        int u = t * 256 + tid;
        int row = u >> 3, cb = u & 7;
        uint32_t so = SWZ((uint32_t)(row * 128 + cb * 16));
        size_t g = gbase + (size_t)row * HD + cb * 8;
        cp16(sb + so, g_k16 + g);
        cp16(sb + 8192 + so, g_v + g);
    }
}

__global__ __launch_bounds__(256, 2) void kv_mma_kernel() {
    extern __shared__ char smem[];
    const uint32_t sm32 = smem_u32(smem);
    const int tid = threadIdx.x, lane = tid & 31, wid = tid >> 5;
    const int bh = blockIdx.x >> 4, sp = blockIdx.x & 15;
    const int wm = wid & 1, wn = wid >> 1;
    const size_t nbase = (size_t)bh * NTOK + sp * (NTOK / KVSPLIT);

    float acc[2][2][4];
#pragma unroll
    for (int i = 0; i < 2; i++)
#pragma unroll
        for (int j = 0; j < 2; j++)
#pragma unroll
            for (int k = 0; k < 4; k++) acc[i][j][k] = 0.f;
    float ksacc = 0.f;
    const int ks_d = tid & 63, ks_q = tid >> 6;

    kv_load_stage(sm32, nbase * HD, tid);
    CP_COMMIT();

    const int l7 = lane & 7, lg = lane >> 3;
    const int an_off = ((lg >> 1) ? 8 : 0) + l7;
    const int ad_off = (lg & 1) ? 8 : 0;
    const int bn_off = ((lg & 1) ? 8 : 0) + l7;
    const int be_off = (lg >> 1) ? 8 : 0;
    const int d0 = wm * 32;
    const int e0 = wn * 16;

    for (int c = 0; c < 4; c++) {
        CP_WAIT0();
        __syncthreads();
        if (c + 1 < 4) {
            kv_load_stage(sm32 + ((c + 1) & 1) * KV_STAGE,
                          (nbase + (c + 1) * 64) * HD, tid);
            CP_COMMIT();
        }
        const uint32_t sb = sm32 + (c & 1) * KV_STAGE;
#pragma unroll
        for (int kk = 0; kk < 64; kk += 16) {
            uint32_t ak[2][4], bv[4];
#pragma unroll
            for (int ma = 0; ma < 2; ma++) {
                uint32_t ad = SWZ((uint32_t)((kk + an_off) * 128 +
                                             (d0 + ma * 16 + ad_off) * 2));
                ldm4t(ak[ma], sb + ad);
            }
            uint32_t bd = SWZ((uint32_t)((kk + bn_off) * 128 + (e0 + be_off) * 2));
            ldm4t(bv, sb + 8192 + bd);
#pragma unroll
            for (int ma = 0; ma < 2; ma++)
#pragma unroll
                for (int nb = 0; nb < 2; nb++)
                    mma16816(acc[ma][nb], ak[ma], bv[nb * 2], bv[nb * 2 + 1]);
        }
#pragma unroll
        for (int nn = 0; nn < 16; nn++) {
            int n = ks_q * 16 + nn;
            uint32_t off = SWZ((uint32_t)(n * 128 + ks_d * 2));
            ksacc += __half2float(*(const __half*)(smem + (c & 1) * KV_STAGE + off));
        }
    }

    float* kssm = (float*)(smem + 2 * KV_STAGE);
    kssm[ks_q * 64 + ks_d] = ksacc;
    __syncthreads();
    if (tid < 64) {
        float s = kssm[tid] + kssm[64 + tid] + kssm[128 + tid] + kssm[192 + tid];
        g_ksum_part[(sp * NBH + bh) * HD + tid] = s;
    }

    const int r0 = lane >> 2, c0 = (lane & 3) * 2;
    __half* kvout = g_kv_part + (size_t)(sp * NBH + bh) * (HD * HD);
#pragma unroll
    for (int ma = 0; ma < 2; ma++)
#pragma unroll
        for (int nb = 0; nb < 2; nb++)
#pragma unroll
            for (int hf = 0; hf < 2; hf++) {
                int d = d0 + ma * 16 + r0 + hf * 8;
                int e = e0 + nb * 8 + c0;
                *(__half2*)(kvout + d * 64 + e) =
                    __halves2half2(__float2half_rn(acc[ma][nb][hf * 2]),
                                   __float2half_rn(acc[ma][nb][hf * 2 + 1]));
            }
}

// ---------------------------------------------------------------------------
// kv reduce: 4 blocks per bh; each reduces a quarter of kv (fp16 partials,
// fp32 accumulate). Quarter 0 also reduces ksum. Writes kvT fp16 + ksum fp32.
// ---------------------------------------------------------------------------
__global__ __launch_bounds__(256) void kv_reduce_kernel() {
    const int bh = blockIdx.x >> 2;
    const int qr = blockIdx.x & 3;
    const int tid = threadIdx.x;
    const int jbase = qr * 1024;

    __shared__ float kvsm[16][65];

    for (int jj = tid; jj < 1024; jj += 256) {
        int j = jbase + jj;
        float s = 0.f;
#pragma unroll
        for (int p = 0; p < KVSPLIT; p++)
            s += __half2float(g_kv_part[(size_t)(p * NBH + bh) * (HD * HD) + j]);
        kvsm[jj >> 6][jj & 63] = s;
    }
    if (qr == 0 && tid < HD) {
        float s = 0.f;
#pragma unroll
        for (int p = 0; p < KVSPLIT; p++)
            s += g_ksum_part[(p * NBH + bh) * HD + tid];
        g_ksum[bh * HD + tid] = s;
    }
    __syncthreads();
    for (int jj = tid; jj < 1024; jj += 256) {
        int dl = jj >> 6;
        int e = jj & 63;
        int d = jbase / 64 + dl;
        g_kvT[(size_t)bh * (HD * HD) + e * HD + d] = __float2half_rn(kvsm[dl][e]);
    }
}

// ---------------------------------------------------------------------------
// attn via mma: num = q @ kvT^T; /(q.ksum+eps); writes attn fp16.
// ---------------------------------------------------------------------------
__global__ __launch_bounds__(256, 2) void attn_mma_kernel() {
    extern __shared__ char smem[];
    const uint32_t sm32 = smem_u32(smem);
    const int tid = threadIdx.x, lane = tid & 31, wid = tid >> 5;
    const int bh = blockIdx.y;
    const int bb = bh >> 4, h = bh & 15;
    const int row0 = blockIdx.x * 128;
    const int wm = wid & 3, wn = wid >> 2;

    {
        size_t qbase = ((size_t)bh * NTOK + row0) * HD;
#pragma unroll
        for (int t = 0; t < 4; t++) {
            int u = t * 256 + tid;
            int row = u >> 3, cb = u & 7;
            uint32_t so = SWZ((uint32_t)(row * 128 + cb * 16));
            cp16(sm32 + AT_Q + so, g_q16 + qbase + (size_t)row * HD + cb * 8);
        }
#pragma unroll
        for (int t = 0; t < 2; t++) {
            int u = t * 256 + tid;
            int row = u >> 3, cb = u & 7;
            uint32_t so = SWZ((uint32_t)(row * 128 + cb * 16));
            cp16(sm32 + AT_KV + so,
                 g_kvT + (size_t)bh * (HD * HD) + (size_t)row * HD + cb * 8);
        }
        if (tid < 64) ((float*)(smem + AT_KSUM))[tid] = g_ksum[bh * HD + tid];
        CP_COMMIT();
        CP_WAIT0();
        __syncthreads();
    }

    {
        int row = tid >> 1, hh = tid & 1;
        float s = 0.f;
        const float* kss = (const float*)(smem + AT_KSUM);
#pragma unroll
        for (int dd = 0; dd < 32; dd++) {
            int d = hh * 32 + dd;
            uint32_t off = SWZ((uint32_t)(row * 128 + d * 2));
            s += __half2float(*(const __half*)(smem + AT_Q + off)) * kss[d];
        }
        s += __shfl_xor_sync(0xFFFFFFFFu, s, 1);
        if (hh == 0) ((float*)(smem + AT_INV))[row] = 1.f / (s + 1e-8f);
        __syncthreads();
    }

    float acc[2][4][4];
#pragma unroll
    for (int i = 0; i < 2; i++)
#pragma unroll
        for (int j = 0; j < 4; j++)
#pragma unroll
            for (int k = 0; k < 4; k++) acc[i][j][k] = 0.f;

    const int a_row = lane & 15;
    const int a_koff = (lane & 16) ? 8 : 0;
    const int b_row = (lane & 7) + ((lane & 16) >> 1);
    const int b_koff = (lane & 8) ? 8 : 0;

#pragma unroll
    for (int kk = 0; kk < 64; kk += 16) {
        uint32_t qa[2][4], kvb[2][4];
#pragma unroll
        for (int ma = 0; ma < 2; ma++) {
            uint32_t ad = SWZ((uint32_t)((wm * 32 + ma * 16 + a_row) * 128 +
                                         (kk + a_koff) * 2));
            ldm4(qa[ma], sm32 + AT_Q + ad);
        }
#pragma unroll
        for (int nb = 0; nb < 2; nb++) {
            uint32_t bd = SWZ((uint32_t)((wn * 32 + nb * 16 + b_row) * 128 +
                                         (kk + b_koff) * 2));
            ldm4(kvb[nb], sm32 + AT_KV + bd);
        }
#pragma unroll
        for (int ma = 0; ma < 2; ma++)
#pragma unroll
            for (int na = 0; na < 4; na++)
                mma16816(acc[ma][na], qa[ma],
                         kvb[na >> 1][(na & 1) * 2], kvb[na >> 1][(na & 1) * 2 + 1]);
    }

    const int r0 = lane >> 2, c0 = (lane & 3) * 2;
    const float* invp = (const float*)(smem + AT_INV);
#pragma unroll
    for (int ma = 0; ma < 2; ma++)
#pragma unroll
        for (int na = 0; na < 4; na++)
#pragma unroll
            for (int hf = 0; hf < 2; hf++) {
                int row = wm * 32 + ma * 16 + r0 + hf * 8;
                float iv = invp[row];
                int e = wn * 32 + na * 8 + c0;
                float v0 = acc[ma][na][hf * 2 + 0] * iv;
                float v1 = acc[ma][na][hf * 2 + 1] * iv;
                size_t ob = ((size_t)(bb * NTOK + row0 + row)) * CDIM + h * HD + e;
                *(__half2*)(g_attn + ob) =
                    __halves2half2(__float2half_rn(v0), __float2half_rn(v1));
            }
}

// ---------------------------------------------------------------------------
extern "C" void kernel_launch(void* const* d_in, const int* in_sizes, int n_in,
                              void* d_out, int out_size) {
    const float* x      = (const float*)d_in[0];
    const float* w_qkv  = (const float*)d_in[1];
    const float* w_proj = (const float*)d_in[2];
    const float* b_proj = (const float*)d_in[3];
    float* out = (float*)d_out;

    cudaFuncSetAttribute(gemm_qkv_mma, cudaFuncAttributeMaxDynamicSharedMemorySize,
                         SMEM_GEMM_BYTES);
    cudaFuncSetAttribute(gemm_proj_mma, cudaFuncAttributeMaxDynamicSharedMemorySize,
                         SMEM_GEMM_BYTES);
    cudaFuncSetAttribute(kv_mma_kernel, cudaFuncAttributeMaxDynamicSharedMemorySize,
                         SMEM_KV_BYTES);
    cudaFuncSetAttribute(attn_mma_kernel, cudaFuncAttributeMaxDynamicSharedMemorySize,
                         SMEM_AT_BYTES);

    conv16_fused_kernel<<<(CVT_TOT_V4 + 255) / 256, 256>>>(x, w_qkv, w_proj);

    gemm_qkv_mma<<<dim3(NQKV / BN, MTOT / BM), 256, SMEM_GEMM_BYTES>>>();

    kv_mma_kernel<<<NBH * KVSPLIT, 256, SMEM_KV_BYTES>>>();
    kv_reduce_kernel<<<NBH * 4, 256>>>();

    attn_mma_kernel<<<dim3(NTOK / 128, NBH), 256, SMEM_AT_BYTES>>>();

    gemm_proj_mma<<<dim3(CDIM / BN, MTOT / BM), 256, SMEM_GEMM_BYTES>>>(b_proj, out);
}

// round 16
// speedup vs baseline: 1.0731x; 1.0081x over previous
#include <cuda_runtime.h>
#include <cuda_fp16.h>
#include <math.h>
#include <stdint.h>

#define NB    4
#define NTOK  4096
#define CDIM  1024
#define NH    16
#define HD    64
#define NBH   64
#define MTOT  16384
#define KDIM  1024
#define NQKV  3072

// GEMM tiling: single-pass fp16, 3-stage pipeline (R9 configuration)
#define BM 128
#define BN 128
#define BK 64
#define NCHUNK (KDIM / BK)      // 16
#define TILE_BYTES (128 * 128)              // 16384
#define OFF_A 0
#define OFF_B TILE_BYTES
#define STAGE_BYTES (2 * TILE_BYTES)        // 32768
#define NSTAGE 3
#define SMEM_GEMM_BYTES (NSTAGE * STAGE_BYTES)  // 98304

// SW128 swizzle
#define SWZ(o) ((o) ^ (((o) >> 3) & 0x70))

#define KVSPLIT 4
#define KV_TOK  (NTOK / KVSPLIT)            // 1024 tokens per block
#define KV_NCH  (KV_TOK / 64)               // 16 chunks
#define KV_STAGE 16384
#define SMEM_KV_BYTES (2 * KV_STAGE + 1024)   // 33792

// attn kernel smem offsets
#define AT_Q    0
#define AT_KV   16384
#define AT_KSUM 24576
#define AT_INV  24832
#define SMEM_AT_BYTES 25344

// fused convert sizes (in float4 units)
#define CVT_X_V4   ((MTOT * KDIM) / 4)
#define CVT_WQ_V4  ((NQKV * KDIM) / 4)
#define CVT_WP_V4  ((CDIM * KDIM) / 4)
#define CVT_TOT_V4 (CVT_X_V4 + CVT_WQ_V4 + CVT_WP_V4)

// ---------------------------------------------------------------------------
// Scratch (device globals)
// ---------------------------------------------------------------------------
__device__ __half g_x16[MTOT * KDIM];
__device__ __half g_wqkv[NQKV * KDIM];
__device__ __half g_wproj[CDIM * KDIM];
__device__ __half g_q16[NBH * NTOK * HD];
__device__ __half g_k16[NBH * NTOK * HD];
__device__ __half g_v[NBH * NTOK * HD];
__device__ __half g_kv_part[KVSPLIT * NBH * HD * HD];   // fp16 partials (2 MB)
__device__ float g_ksum_part[KVSPLIT * NBH * HD];
__device__ float g_ksum[NBH * HD];
__device__ __half g_kvT[NBH * HD * HD];
__device__ __half g_attn[MTOT * CDIM];

__device__ __forceinline__ float elu1(float x) {
    return x > 0.f ? x + 1.f : expf(x);
}

// ---------------------------------------------------------------------------
// PTX helpers (compute_103-safe)
// ---------------------------------------------------------------------------
__device__ __forceinline__ uint32_t smem_u32(const void* p) {
    uint32_t a;
    asm("{ .reg .u64 t; cvta.to.shared.u64 t, %1; cvt.u32.u64 %0, t; }" : "=r"(a) : "l"(p));
    return a;
}
__device__ __forceinline__ void cp16(uint32_t s, const void* g) {
    asm volatile("cp.async.cg.shared.global [%0], [%1], 16;" :: "r"(s), "l"(g));
}
#define CP_COMMIT() asm volatile("cp.async.commit_group;" ::: "memory")
#define CP_WAIT1()  asm volatile("cp.async.wait_group 1;" ::: "memory")
#define CP_WAIT0()  asm volatile("cp.async.wait_group 0;" ::: "memory")

__device__ __forceinline__ void ldm4(uint32_t* r, uint32_t addr) {
    asm volatile("ldmatrix.sync.aligned.m8n8.x4.shared.b16 {%0,%1,%2,%3}, [%4];"
                 : "=r"(r[0]), "=r"(r[1]), "=r"(r[2]), "=r"(r[3]) : "r"(addr));
}
__device__ __forceinline__ void ldm4t(uint32_t* r, uint32_t addr) {
    asm volatile("ldmatrix.sync.aligned.m8n8.x4.trans.shared.b16 {%0,%1,%2,%3}, [%4];"
                 : "=r"(r[0]), "=r"(r[1]), "=r"(r[2]), "=r"(r[3]) : "r"(addr));
}
__device__ __forceinline__ void mma16816(float* d, const uint32_t* a,
                                         uint32_t b0, uint32_t b1) {
    asm volatile(
        "mma.sync.aligned.m16n8k16.row.col.f32.f16.f16.f32 "
        "{%0,%1,%2,%3}, {%4,%5,%6,%7}, {%8,%9}, {%0,%1,%2,%3};"
        : "+f"(d[0]), "+f"(d[1]), "+f"(d[2]), "+f"(d[3])
        : "r"(a[0]), "r"(a[1]), "r"(a[2]), "r"(a[3]), "r"(b0), "r"(b1));
}

// ---------------------------------------------------------------------------
// GEMM stage loader (A, B): 128x64 fp16 tiles, SW128 rows. 8 cp16/thread.
// ---------------------------------------------------------------------------
__device__ __forceinline__ void load_stage(
    uint32_t sbase,
    const __half* __restrict__ A, const __half* __restrict__ B,
    int m0, int n0, int kc, int tid)
{
#pragma unroll
    for (int t = 0; t < 4; t++) {
        int idx = t * 256 + tid;
        int row = idx >> 3;
        int c16 = idx & 7;
        uint32_t so = SWZ((uint32_t)(row * 128 + c16 * 16));
        cp16(sbase + OFF_A + so, A + (size_t)(m0 + row) * KDIM + kc + c16 * 8);
        cp16(sbase + OFF_B + so, B + (size_t)(n0 + row) * KDIM + kc + c16 * 8);
    }
}

// ---------------------------------------------------------------------------
// GEMM mainloop: acc[2][8][4] += A*B over K=1024. Single pass, 3-stage.
// (R9 configuration: 8 warps x 32x64 warp tile, 256 threads, 2 CTA/SM.)
// ---------------------------------------------------------------------------
__device__ __forceinline__ void mma_mainloop(
    const __half* __restrict__ A, const __half* __restrict__ B,
    int m0, int n0, uint32_t sm32, float acc[2][8][4])
{
    const int tid = threadIdx.x;
    const int lane = tid & 31;
    const int wid = tid >> 5;
    const int wm = wid & 3;
    const int wn = wid >> 2;

    load_stage(sm32, A, B, m0, n0, 0, tid);
    CP_COMMIT();
    load_stage(sm32 + STAGE_BYTES, A, B, m0, n0, BK, tid);
    CP_COMMIT();

    const int a_row = (lane & 15);
    const int a_koff = (lane & 16) ? 8 : 0;
    const int b_row = (lane & 7) + ((lane & 16) >> 1);
    const int b_koff = (lane & 8) ? 8 : 0;

    const uint32_t aoff0 = (uint32_t)((wm * 32 + a_row) * 128 + a_koff * 2);
    const uint32_t aoff1 = aoff0 + 16 * 128;
    uint32_t boffs[4];
#pragma unroll
    for (int nb = 0; nb < 4; nb++)
        boffs[nb] = (uint32_t)((wn * 64 + nb * 16 + b_row) * 128 + b_koff * 2);

    int cur = 0, pre = 2;
    for (int c = 0; c < NCHUNK; c++) {
        if (c == NCHUNK - 1) CP_WAIT0(); else CP_WAIT1();
        __syncthreads();

        if (c + 2 < NCHUNK) {
            load_stage(sm32 + pre * STAGE_BYTES, A, B, m0, n0, (c + 2) * BK, tid);
            CP_COMMIT();
        }

        const uint32_t sb = sm32 + cur * STAGE_BYTES;
#pragma unroll
        for (int kk = 0; kk < BK; kk += 16) {
            uint32_t aa[2][4], bb[4][4];
            const uint32_t kb = (uint32_t)(kk * 2);
            ldm4(aa[0], sb + OFF_A + SWZ(aoff0 + kb));
            ldm4(aa[1], sb + OFF_A + SWZ(aoff1 + kb));
#pragma unroll
            for (int nb = 0; nb < 4; nb++)
                ldm4(bb[nb], sb + OFF_B + SWZ(boffs[nb] + kb));
#pragma unroll
            for (int ma = 0; ma < 2; ma++)
#pragma unroll
                for (int na = 0; na < 8; na++)
                    mma16816(acc[ma][na], aa[ma],
                             bb[na >> 1][(na & 1) * 2], bb[na >> 1][(na & 1) * 2 + 1]);
        }
        cur = (cur == NSTAGE - 1) ? 0 : cur + 1;
        pre = (pre == NSTAGE - 1) ? 0 : pre + 1;
    }
}

// ---------------------------------------------------------------------------
// QKV GEMM: epilogue applies elu+1 to q,k; writes q,k,v single fp16.
// ---------------------------------------------------------------------------
__global__ __launch_bounds__(256, 2) void gemm_qkv_mma() {
    extern __shared__ char smem[];
    const uint32_t sm32 = smem_u32(smem);
    const int m0 = blockIdx.y * BM;
    const int n0 = blockIdx.x * BN;

    float acc[2][8][4];
#pragma unroll
    for (int i = 0; i < 2; i++)
#pragma unroll
        for (int j = 0; j < 8; j++)
#pragma unroll
            for (int k = 0; k < 4; k++) acc[i][j][k] = 0.f;

    mma_mainloop(g_x16, g_wqkv, m0, n0, sm32, acc);

    const int tid = threadIdx.x;
    const int lane = tid & 31;
    const int wid = tid >> 5;
    const int wm = wid & 3, wn = wid >> 2;
    const int r0 = lane >> 2;
    const int c0 = (lane & 3) * 2;

#pragma unroll
    for (int ma = 0; ma < 2; ma++) {
#pragma unroll
        for (int na = 0; na < 8; na++) {
            const int colg = n0 + wn * 64 + na * 8 + c0;
            const int part = colg >> 10;
            const int h = (colg & 1023) >> 6;
            const int d = colg & 63;
            __half* dst = (part == 0) ? g_q16 : (part == 1) ? g_k16 : g_v;
            const bool feat = part < 2;
#pragma unroll
            for (int hf = 0; hf < 2; hf++) {
                const int m = m0 + wm * 32 + ma * 16 + r0 + hf * 8;
                const int bb = m >> 12, t = m & 4095;
                float v0 = acc[ma][na][hf * 2 + 0];
                float v1 = acc[ma][na][hf * 2 + 1];
                if (feat) { v0 = elu1(v0); v1 = elu1(v1); }
                size_t off = ((size_t)(bb * NH + h) * NTOK + t) * HD + d;
                *(__half2*)(dst + off) =
                    __halves2half2(__float2half_rn(v0), __float2half_rn(v1));
            }
        }
    }
}

// ---------------------------------------------------------------------------
// Proj GEMM: out = attn @ w_proj^T + bias
// ---------------------------------------------------------------------------
__global__ __launch_bounds__(256, 2) void gemm_proj_mma(const float* __restrict__ bias,
                                                        float* __restrict__ out) {
    extern __shared__ char smem[];
    const uint32_t sm32 = smem_u32(smem);
    const int m0 = blockIdx.y * BM;
    const int n0 = blockIdx.x * BN;

    float acc[2][8][4];
#pragma unroll
    for (int i = 0; i < 2; i++)
#pragma unroll
        for (int j = 0; j < 8; j++)
#pragma unroll
            for (int k = 0; k < 4; k++) acc[i][j][k] = 0.f;

    mma_mainloop(g_attn, g_wproj, m0, n0, sm32, acc);

    const int tid = threadIdx.x;
    const int lane = tid & 31;
    const int wid = tid >> 5;
    const int wm = wid & 3, wn = wid >> 2;
    const int r0 = lane >> 2;
    const int c0 = (lane & 3) * 2;

#pragma unroll
    for (int ma = 0; ma < 2; ma++) {
#pragma unroll
        for (int na = 0; na < 8; na++) {
            const int colg = n0 + wn * 64 + na * 8 + c0;
            const float b0 = bias[colg], b1 = bias[colg + 1];
#pragma unroll
            for (int hf = 0; hf < 2; hf++) {
                const int m = m0 + wm * 32 + ma * 16 + r0 + hf * 8;
                float2 o = make_float2(acc[ma][na][hf * 2 + 0] + b0,
                                       acc[ma][na][hf * 2 + 1] + b1);
                *(float2*)(out + (size_t)m * CDIM + colg) = o;
            }
        }
    }
}

// ---------------------------------------------------------------------------
// Fused fp32 -> fp16 convert for x, w_qkv, w_proj in ONE launch.
// ---------------------------------------------------------------------------
__global__ void conv16_fused_kernel(const float* __restrict__ x,
                                    const float* __restrict__ wq,
                                    const float* __restrict__ wp) {
    int i4 = blockIdx.x * blockDim.x + threadIdx.x;
    if (i4 >= CVT_TOT_V4) return;
    const float* src;
    __half* dst;
    int off4;
    if (i4 < CVT_X_V4) {
        src = x; dst = g_x16; off4 = i4;
    } else if (i4 < CVT_X_V4 + CVT_WQ_V4) {
        src = wq; dst = g_wqkv; off4 = i4 - CVT_X_V4;
    } else {
        src = wp; dst = g_wproj; off4 = i4 - CVT_X_V4 - CVT_WQ_V4;
    }
    int i = off4 * 4;
    float4 v = *(const float4*)(src + i);
    *(__half2*)(dst + i)     = __halves2half2(__float2half_rn(v.x), __float2half_rn(v.y));
    *(__half2*)(dst + i + 2) = __halves2half2(__float2half_rn(v.z), __float2half_rn(v.w));
}

// ---------------------------------------------------------------------------
// kv via mma: per (bh, 1/4 split of 1024 tokens): kv[64d][64e] = k^T v;
// ksum side reduction. Partials stored fp16. 256 blocks = one wave.
// ---------------------------------------------------------------------------
__device__ __forceinline__ void kv_load_stage(uint32_t sb, size_t gbase, int tid) {
#pragma unroll
    for (int t = 0; t < 2; t++) {
        int u = t * 256 + tid;
        int row = u >> 3, cb = u & 7;
        uint32_t so = SWZ((uint32_t)(row * 128 + cb * 16));
        size_t g = gbase + (size_t)row * HD + cb * 8;
        cp16(sb + so, g_k16 + g);
        cp16(sb + 8192 + so, g_v + g);
    }
}

__global__ __launch_bounds__(256, 2) void kv_mma_kernel() {
    extern __shared__ char smem[];
    const uint32_t sm32 = smem_u32(smem);
    const int tid = threadIdx.x, lane = tid & 31, wid = tid >> 5;
    const int bh = blockIdx.x >> 2, sp = blockIdx.x & 3;
    const int wm = wid & 1, wn = wid >> 1;
    const size_t nbase = (size_t)bh * NTOK + sp * KV_TOK;

    float acc[2][2][4];
#pragma unroll
    for (int i = 0; i < 2; i++)
#pragma unroll
        for (int j = 0; j < 2; j++)
#pragma unroll
            for (int k = 0; k < 4; k++) acc[i][j][k] = 0.f;
    float ksacc = 0.f;
    const int ks_d = tid & 63, ks_q = tid >> 6;

    kv_load_stage(sm32, nbase * HD, tid);
    CP_COMMIT();

    const int l7 = lane & 7, lg = lane >> 3;
    const int an_off = ((lg >> 1) ? 8 : 0) + l7;
    const int ad_off = (lg & 1) ? 8 : 0;
    const int bn_off = ((lg & 1) ? 8 : 0) + l7;
    const int be_off = (lg >> 1) ? 8 : 0;
    const int d0 = wm * 32;
    const int e0 = wn * 16;

    for (int c = 0; c < KV_NCH; c++) {
        CP_WAIT0();
        __syncthreads();
        if (c + 1 < KV_NCH) {
            kv_load_stage(sm32 + ((c + 1) & 1) * KV_STAGE,
                          (nbase + (size_t)(c + 1) * 64) * HD, tid);
            CP_COMMIT();
        }
        const uint32_t sb = sm32 + (c & 1) * KV_STAGE;
#pragma unroll
        for (int kk = 0; kk < 64; kk += 16) {
            uint32_t ak[2][4], bv[4];
#pragma unroll
            for (int ma = 0; ma < 2; ma++) {
                uint32_t ad = SWZ((uint32_t)((kk + an_off) * 128 +
                                             (d0 + ma * 16 + ad_off) * 2));
                ldm4t(ak[ma], sb + ad);
            }
            uint32_t bd = SWZ((uint32_t)((kk + bn_off) * 128 + (e0 + be_off) * 2));
            ldm4t(bv, sb + 8192 + bd);
#pragma unroll
            for (int ma = 0; ma < 2; ma++)
#pragma unroll
                for (int nb = 0; nb < 2; nb++)
                    mma16816(acc[ma][nb], ak[ma], bv[nb * 2], bv[nb * 2 + 1]);
        }
#pragma unroll
        for (int nn = 0; nn < 16; nn++) {
            int n = ks_q * 16 + nn;
            uint32_t off = SWZ((uint32_t)(n * 128 + ks_d * 2));
            ksacc += __half2float(*(const __half*)(smem + (c & 1) * KV_STAGE + off));
        }
    }

    float* kssm = (float*)(smem + 2 * KV_STAGE);
    kssm[ks_q * 64 + ks_d] = ksacc;
    __syncthreads();
    if (tid < 64) {
        float s = kssm[tid] + kssm[64 + tid] + kssm[128 + tid] + kssm[192 + tid];
        g_ksum_part[(sp * NBH + bh) * HD + tid] = s;
    }

    const int r0 = lane >> 2, c0 = (lane & 3) * 2;
    __half* kvout = g_kv_part + (size_t)(sp * NBH + bh) * (HD * HD);
#pragma unroll
    for (int ma = 0; ma < 2; ma++)
#pragma unroll
        for (int nb = 0; nb < 2; nb++)
#pragma unroll
            for (int hf = 0; hf < 2; hf++) {
                int d = d0 + ma * 16 + r0 + hf * 8;
                int e = e0 + nb * 8 + c0;
                *(__half2*)(kvout + d * 64 + e) =
                    __halves2half2(__float2half_rn(acc[ma][nb][hf * 2]),
                                   __float2half_rn(acc[ma][nb][hf * 2 + 1]));
            }
}

// ---------------------------------------------------------------------------
// kv reduce: 4 blocks per bh; each reduces a quarter of kv (fp16 partials,
// fp32 accumulate, 4 partials). Quarter 0 also reduces ksum.
// ---------------------------------------------------------------------------
__global__ __launch_bounds__(256) void kv_reduce_kernel() {
    const int bh = blockIdx.x >> 2;
    const int qr = blockIdx.x & 3;
    const int tid = threadIdx.x;
    const int jbase = qr * 1024;

    __shared__ float kvsm[16][65];

    for (int jj = tid; jj < 1024; jj += 256) {
        int j = jbase + jj;
        float s = 0.f;
#pragma unroll
        for (int p = 0; p < KVSPLIT; p++)
            s += __half2float(g_kv_part[(size_t)(p * NBH + bh) * (HD * HD) + j]);
        kvsm[jj >> 6][jj & 63] = s;
    }
    if (qr == 0 && tid < HD) {
        float s = 0.f;
#pragma unroll
        for (int p = 0; p < KVSPLIT; p++)
            s += g_ksum_part[(p * NBH + bh) * HD + tid];
        g_ksum[bh * HD + tid] = s;
    }
    __syncthreads();
    for (int jj = tid; jj < 1024; jj += 256) {
        int dl = jj >> 6;
        int e = jj & 63;
        int d = jbase / 64 + dl;
        g_kvT[(size_t)bh * (HD * HD) + e * HD + d] = __float2half_rn(kvsm[dl][e]);
    }
}

// ---------------------------------------------------------------------------
// attn via mma: num = q @ kvT^T; /(q.ksum+eps); writes attn fp16.
// ---------------------------------------------------------------------------
__global__ __launch_bounds__(256, 2) void attn_mma_kernel() {
    extern __shared__ char smem[];
    const uint32_t sm32 = smem_u32(smem);
    const int tid = threadIdx.x, lane = tid & 31, wid = tid >> 5;
    const int bh = blockIdx.y;
    const int bb = bh >> 4, h = bh & 15;
    const int row0 = blockIdx.x * 128;
    const int wm = wid & 3, wn = wid >> 2;

    {
        size_t qbase = ((size_t)bh * NTOK + row0) * HD;
#pragma unroll
        for (int t = 0; t < 4; t++) {
            int u = t * 256 + tid;
            int row = u >> 3, cb = u & 7;
            uint32_t so = SWZ((uint32_t)(row * 128 + cb * 16));
            cp16(sm32 + AT_Q + so, g_q16 + qbase + (size_t)row * HD + cb * 8);
        }
#pragma unroll
        for (int t = 0; t < 2; t++) {
            int u = t * 256 + tid;
            int row = u >> 3, cb = u & 7;
            uint32_t so = SWZ((uint32_t)(row * 128 + cb * 16));
            cp16(sm32 + AT_KV + so,
                 g_kvT + (size_t)bh * (HD * HD) + (size_t)row * HD + cb * 8);
        }
        if (tid < 64) ((float*)(smem + AT_KSUM))[tid] = g_ksum[bh * HD + tid];
        CP_COMMIT();
        CP_WAIT0();
        __syncthreads();
    }

    {
        int row = tid >> 1, hh = tid & 1;
        float s = 0.f;
        const float* kss = (const float*)(smem + AT_KSUM);
#pragma unroll
        for (int dd = 0; dd < 32; dd++) {
            int d = hh * 32 + dd;
            uint32_t off = SWZ((uint32_t)(row * 128 + d * 2));
            s += __half2float(*(const __half*)(smem + AT_Q + off)) * kss[d];
        }
        s += __shfl_xor_sync(0xFFFFFFFFu, s, 1);
        if (hh == 0) ((float*)(smem + AT_INV))[row] = 1.f / (s + 1e-8f);
        __syncthreads();
    }

    float acc[2][4][4];
#pragma unroll
    for (int i = 0; i < 2; i++)
#pragma unroll
        for (int j = 0; j < 4; j++)
#pragma unroll
            for (int k = 0; k < 4; k++) acc[i][j][k] = 0.f;

    const int a_row = lane & 15;
    const int a_koff = (lane & 16) ? 8 : 0;
    const int b_row = (lane & 7) + ((lane & 16) >> 1);
    const int b_koff = (lane & 8) ? 8 : 0;

#pragma unroll
    for (int kk = 0; kk < 64; kk += 16) {
        uint32_t qa[2][4], kvb[2][4];
#pragma unroll
        for (int ma = 0; ma < 2; ma++) {
            uint32_t ad = SWZ((uint32_t)((wm * 32 + ma * 16 + a_row) * 128 +
                                         (kk + a_koff) * 2));
            ldm4(qa[ma], sm32 + AT_Q + ad);
        }
#pragma unroll
        for (int nb = 0; nb < 2; nb++) {
            uint32_t bd = SWZ((uint32_t)((wn * 32 + nb * 16 + b_row) * 128 +
                                         (kk + b_koff) * 2));
            ldm4(kvb[nb], sm32 + AT_KV + bd);
        }
#pragma unroll
        for (int ma = 0; ma < 2; ma++)
#pragma unroll
            for (int na = 0; na < 4; na++)
                mma16816(acc[ma][na], qa[ma],
                         kvb[na >> 1][(na & 1) * 2], kvb[na >> 1][(na & 1) * 2 + 1]);
    }

    const int r0 = lane >> 2, c0 = (lane & 3) * 2;
    const float* invp = (const float*)(smem + AT_INV);
#pragma unroll
    for (int ma = 0; ma < 2; ma++)
#pragma unroll
        for (int na = 0; na < 4; na++)
#pragma unroll
            for (int hf = 0; hf < 2; hf++) {
                int row = wm * 32 + ma * 16 + r0 + hf * 8;
                float iv = invp[row];
                int e = wn * 32 + na * 8 + c0;
                float v0 = acc[ma][na][hf * 2 + 0] * iv;
                float v1 = acc[ma][na][hf * 2 + 1] * iv;
                size_t ob = ((size_t)(bb * NTOK + row0 + row)) * CDIM + h * HD + e;
                *(__half2*)(g_attn + ob) =
                    __halves2half2(__float2half_rn(v0), __float2half_rn(v1));
            }
}

// ---------------------------------------------------------------------------
extern "C" void kernel_launch(void* const* d_in, const int* in_sizes, int n_in,
                              void* d_out, int out_size) {
    const float* x      = (const float*)d_in[0];
    const float* w_qkv  = (const float*)d_in[1];
    const float* w_proj = (const float*)d_in[2];
    const float* b_proj = (const float*)d_in[3];
    float* out = (float*)d_out;

    cudaFuncSetAttribute(gemm_qkv_mma, cudaFuncAttributeMaxDynamicSharedMemorySize,
                         SMEM_GEMM_BYTES);
    cudaFuncSetAttribute(gemm_proj_mma, cudaFuncAttributeMaxDynamicSharedMemorySize,
                         SMEM_GEMM_BYTES);
    cudaFuncSetAttribute(kv_mma_kernel, cudaFuncAttributeMaxDynamicSharedMemorySize,
                         SMEM_KV_BYTES);
    cudaFuncSetAttribute(attn_mma_kernel, cudaFuncAttributeMaxDynamicSharedMemorySize,
                         SMEM_AT_BYTES);

    conv16_fused_kernel<<<(CVT_TOT_V4 + 255) / 256, 256>>>(x, w_qkv, w_proj);

    gemm_qkv_mma<<<dim3(NQKV / BN, MTOT / BM), 256, SMEM_GEMM_BYTES>>>();

    kv_mma_kernel<<<NBH * KVSPLIT, 256, SMEM_KV_BYTES>>>();
    kv_reduce_kernel<<<NBH * 4, 256>>>();

    attn_mma_kernel<<<dim3(NTOK / 128, NBH), 256, SMEM_AT_BYTES>>>();

    gemm_proj_mma<<<dim3(CDIM / BN, MTOT / BM), 256, SMEM_GEMM_BYTES>>>(b_proj, out);
}

// round 17
// speedup vs baseline: 1.0892x; 1.0151x over previous
#include <cuda_runtime.h>
#include <cuda_fp16.h>
#include <math.h>
#include <stdint.h>

#define NB    4
#define NTOK  4096
#define CDIM  1024
#define NH    16
#define HD    64
#define NBH   64
#define MTOT  16384
#define KDIM  1024
#define NQKV  3072

// GEMM tiling: single-pass fp16, 3-stage pipeline (R9 configuration)
#define BM 128
#define BN 128
#define BK 64
#define NCHUNK (KDIM / BK)      // 16
#define TILE_BYTES (128 * 128)              // 16384
#define OFF_A 0
#define OFF_B TILE_BYTES
#define STAGE_BYTES (2 * TILE_BYTES)        // 32768
#define NSTAGE 3
#define SMEM_GEMM_BYTES (NSTAGE * STAGE_BYTES)  // 98304

// SW128 swizzle
#define SWZ(o) ((o) ^ (((o) >> 3) & 0x70))

#define KVSPLIT 4
#define KV_TOK  (NTOK / KVSPLIT)            // 1024 tokens per block
#define KV_NCH  (KV_TOK / 64)               // 16 chunks
#define KV_STAGE 16384
#define SMEM_KV_BYTES (2 * KV_STAGE + 1024)   // 33792

// attn kernel smem offsets
#define AT_Q    0
#define AT_KV   16384
#define AT_KSUM 24576
#define AT_INV  24832
#define SMEM_AT_BYTES 25344

// fused convert sizes (in float8 = 2x float4 units)
#define CVT_X_V8   ((MTOT * KDIM) / 8)
#define CVT_WQ_V8  ((NQKV * KDIM) / 8)
#define CVT_WP_V8  ((CDIM * KDIM) / 8)
#define CVT_TOT_V8 (CVT_X_V8 + CVT_WQ_V8 + CVT_WP_V8)

// ---------------------------------------------------------------------------
// Scratch (device globals)
// ---------------------------------------------------------------------------
__device__ __half g_x16[MTOT * KDIM];
__device__ __half g_wqkv[NQKV * KDIM];
__device__ __half g_wproj[CDIM * KDIM];
__device__ __half g_q16[NBH * NTOK * HD];
__device__ __half g_k16[NBH * NTOK * HD];
__device__ __half g_v[NBH * NTOK * HD];
__device__ __half g_kv_part[KVSPLIT * NBH * HD * HD];   // fp16 partials (2 MB)
__device__ float g_ksum_part[KVSPLIT * NBH * HD];
__device__ float g_ksum[NBH * HD];
__device__ __half g_kvT[NBH * HD * HD];
__device__ __half g_attn[MTOT * CDIM];

__device__ __forceinline__ float elu1(float x) {
    return x > 0.f ? x + 1.f : expf(x);
}

// ---------------------------------------------------------------------------
// PTX helpers (compute_103-safe)
// ---------------------------------------------------------------------------
__device__ __forceinline__ uint32_t smem_u32(const void* p) {
    uint32_t a;
    asm("{ .reg .u64 t; cvta.to.shared.u64 t, %1; cvt.u32.u64 %0, t; }" : "=r"(a) : "l"(p));
    return a;
}
__device__ __forceinline__ void cp16(uint32_t s, const void* g) {
    asm volatile("cp.async.cg.shared.global [%0], [%1], 16;" :: "r"(s), "l"(g));
}
#define CP_COMMIT() asm volatile("cp.async.commit_group;" ::: "memory")
#define CP_WAIT1()  asm volatile("cp.async.wait_group 1;" ::: "memory")
#define CP_WAIT0()  asm volatile("cp.async.wait_group 0;" ::: "memory")

__device__ __forceinline__ void ldm4(uint32_t* r, uint32_t addr) {
    asm volatile("ldmatrix.sync.aligned.m8n8.x4.shared.b16 {%0,%1,%2,%3}, [%4];"
                 : "=r"(r[0]), "=r"(r[1]), "=r"(r[2]), "=r"(r[3]) : "r"(addr));
}
__device__ __forceinline__ void ldm4t(uint32_t* r, uint32_t addr) {
    asm volatile("ldmatrix.sync.aligned.m8n8.x4.trans.shared.b16 {%0,%1,%2,%3}, [%4];"
                 : "=r"(r[0]), "=r"(r[1]), "=r"(r[2]), "=r"(r[3]) : "r"(addr));
}
__device__ __forceinline__ void mma16816(float* d, const uint32_t* a,
                                         uint32_t b0, uint32_t b1) {
    asm volatile(
        "mma.sync.aligned.m16n8k16.row.col.f32.f16.f16.f32 "
        "{%0,%1,%2,%3}, {%4,%5,%6,%7}, {%8,%9}, {%0,%1,%2,%3};"
        : "+f"(d[0]), "+f"(d[1]), "+f"(d[2]), "+f"(d[3])
        : "r"(a[0]), "r"(a[1]), "r"(a[2]), "r"(a[3]), "r"(b0), "r"(b1));
}

// ---------------------------------------------------------------------------
// GEMM stage loader (A, B): 128x64 fp16 tiles, SW128 rows. 8 cp16/thread.
// ---------------------------------------------------------------------------
__device__ __forceinline__ void load_stage(
    uint32_t sbase,
    const __half* __restrict__ A, const __half* __restrict__ B,
    int m0, int n0, int kc, int tid)
{
#pragma unroll
    for (int t = 0; t < 4; t++) {
        int idx = t * 256 + tid;
        int row = idx >> 3;
        int c16 = idx & 7;
        uint32_t so = SWZ((uint32_t)(row * 128 + c16 * 16));
        cp16(sbase + OFF_A + so, A + (size_t)(m0 + row) * KDIM + kc + c16 * 8);
        cp16(sbase + OFF_B + so, B + (size_t)(n0 + row) * KDIM + kc + c16 * 8);
    }
}

// ---------------------------------------------------------------------------
// GEMM mainloop: acc[2][8][4] += A*B over K=1024. Single pass, 3-stage.
// (R9 configuration: 8 warps x 32x64 warp tile, 256 threads, 2 CTA/SM.)
// ---------------------------------------------------------------------------
__device__ __forceinline__ void mma_mainloop(
    const __half* __restrict__ A, const __half* __restrict__ B,
    int m0, int n0, uint32_t sm32, float acc[2][8][4])
{
    const int tid = threadIdx.x;
    const int lane = tid & 31;
    const int wid = tid >> 5;
    const int wm = wid & 3;
    const int wn = wid >> 2;

    load_stage(sm32, A, B, m0, n0, 0, tid);
    CP_COMMIT();
    load_stage(sm32 + STAGE_BYTES, A, B, m0, n0, BK, tid);
    CP_COMMIT();

    const int a_row = (lane & 15);
    const int a_koff = (lane & 16) ? 8 : 0;
    const int b_row = (lane & 7) + ((lane & 16) >> 1);
    const int b_koff = (lane & 8) ? 8 : 0;

    const uint32_t aoff0 = (uint32_t)((wm * 32 + a_row) * 128 + a_koff * 2);
    const uint32_t aoff1 = aoff0 + 16 * 128;
    uint32_t boffs[4];
#pragma unroll
    for (int nb = 0; nb < 4; nb++)
        boffs[nb] = (uint32_t)((wn * 64 + nb * 16 + b_row) * 128 + b_koff * 2);

    int cur = 0, pre = 2;
    for (int c = 0; c < NCHUNK; c++) {
        if (c == NCHUNK - 1) CP_WAIT0(); else CP_WAIT1();
        __syncthreads();

        if (c + 2 < NCHUNK) {
            load_stage(sm32 + pre * STAGE_BYTES, A, B, m0, n0, (c + 2) * BK, tid);
            CP_COMMIT();
        }

        const uint32_t sb = sm32 + cur * STAGE_BYTES;
#pragma unroll
        for (int kk = 0; kk < BK; kk += 16) {
            uint32_t aa[2][4], bb[4][4];
            const uint32_t kb = (uint32_t)(kk * 2);
            ldm4(aa[0], sb + OFF_A + SWZ(aoff0 + kb));
            ldm4(aa[1], sb + OFF_A + SWZ(aoff1 + kb));
#pragma unroll
            for (int nb = 0; nb < 4; nb++)
                ldm4(bb[nb], sb + OFF_B + SWZ(boffs[nb] + kb));
#pragma unroll
            for (int ma = 0; ma < 2; ma++)
#pragma unroll
                for (int na = 0; na < 8; na++)
                    mma16816(acc[ma][na], aa[ma],
                             bb[na >> 1][(na & 1) * 2], bb[na >> 1][(na & 1) * 2 + 1]);
        }
        cur = (cur == NSTAGE - 1) ? 0 : cur + 1;
        pre = (pre == NSTAGE - 1) ? 0 : pre + 1;
    }
}

// ---------------------------------------------------------------------------
// QKV GEMM: epilogue applies elu+1 to q,k; writes q,k,v single fp16.
// ---------------------------------------------------------------------------
__global__ __launch_bounds__(256, 2) void gemm_qkv_mma() {
    extern __shared__ char smem[];
    const uint32_t sm32 = smem_u32(smem);
    const int m0 = blockIdx.y * BM;
    const int n0 = blockIdx.x * BN;

    float acc[2][8][4];
#pragma unroll
    for (int i = 0; i < 2; i++)
#pragma unroll
        for (int j = 0; j < 8; j++)
#pragma unroll
            for (int k = 0; k < 4; k++) acc[i][j][k] = 0.f;

    mma_mainloop(g_x16, g_wqkv, m0, n0, sm32, acc);

    const int tid = threadIdx.x;
    const int lane = tid & 31;
    const int wid = tid >> 5;
    const int wm = wid & 3, wn = wid >> 2;
    const int r0 = lane >> 2;
    const int c0 = (lane & 3) * 2;

#pragma unroll
    for (int ma = 0; ma < 2; ma++) {
#pragma unroll
        for (int na = 0; na < 8; na++) {
            const int colg = n0 + wn * 64 + na * 8 + c0;
            const int part = colg >> 10;
            const int h = (colg & 1023) >> 6;
            const int d = colg & 63;
            __half* dst = (part == 0) ? g_q16 : (part == 1) ? g_k16 : g_v;
            const bool feat = part < 2;
#pragma unroll
            for (int hf = 0; hf < 2; hf++) {
                const int m = m0 + wm * 32 + ma * 16 + r0 + hf * 8;
                const int bb = m >> 12, t = m & 4095;
                float v0 = acc[ma][na][hf * 2 + 0];
                float v1 = acc[ma][na][hf * 2 + 1];
                if (feat) { v0 = elu1(v0); v1 = elu1(v1); }
                size_t off = ((size_t)(bb * NH + h) * NTOK + t) * HD + d;
                *(__half2*)(dst + off) =
                    __halves2half2(__float2half_rn(v0), __float2half_rn(v1));
            }
        }
    }
}

// ---------------------------------------------------------------------------
// Proj GEMM: out = attn @ w_proj^T + bias
// ---------------------------------------------------------------------------
__global__ __launch_bounds__(256, 2) void gemm_proj_mma(const float* __restrict__ bias,
                                                        float* __restrict__ out) {
    extern __shared__ char smem[];
    const uint32_t sm32 = smem_u32(smem);
    const int m0 = blockIdx.y * BM;
    const int n0 = blockIdx.x * BN;

    float acc[2][8][4];
#pragma unroll
    for (int i = 0; i < 2; i++)
#pragma unroll
        for (int j = 0; j < 8; j++)
#pragma unroll
            for (int k = 0; k < 4; k++) acc[i][j][k] = 0.f;

    mma_mainloop(g_attn, g_wproj, m0, n0, sm32, acc);

    const int tid = threadIdx.x;
    const int lane = tid & 31;
    const int wid = tid >> 5;
    const int wm = wid & 3, wn = wid >> 2;
    const int r0 = lane >> 2;
    const int c0 = (lane & 3) * 2;

#pragma unroll
    for (int ma = 0; ma < 2; ma++) {
#pragma unroll
        for (int na = 0; na < 8; na++) {
            const int colg = n0 + wn * 64 + na * 8 + c0;
            const float b0 = bias[colg], b1 = bias[colg + 1];
#pragma unroll
            for (int hf = 0; hf < 2; hf++) {
                const int m = m0 + wm * 32 + ma * 16 + r0 + hf * 8;
                float2 o = make_float2(acc[ma][na][hf * 2 + 0] + b0,
                                       acc[ma][na][hf * 2 + 1] + b1);
                *(float2*)(out + (size_t)m * CDIM + colg) = o;
            }
        }
    }
}

// ---------------------------------------------------------------------------
// Fused fp32 -> fp16 convert (x, w_qkv, w_proj), 8 floats per thread.
// ---------------------------------------------------------------------------
__global__ void conv16_fused_kernel(const float* __restrict__ x,
                                    const float* __restrict__ wq,
                                    const float* __restrict__ wp) {
    int i8 = blockIdx.x * blockDim.x + threadIdx.x;
    if (i8 >= CVT_TOT_V8) return;
    const float* src;
    __half* dst;
    int off8;
    if (i8 < CVT_X_V8) {
        src = x; dst = g_x16; off8 = i8;
    } else if (i8 < CVT_X_V8 + CVT_WQ_V8) {
        src = wq; dst = g_wqkv; off8 = i8 - CVT_X_V8;
    } else {
        src = wp; dst = g_wproj; off8 = i8 - CVT_X_V8 - CVT_WQ_V8;
    }
    int i = off8 * 8;
    float4 a = *(const float4*)(src + i);
    float4 b = *(const float4*)(src + i + 4);
    *(__half2*)(dst + i)     = __halves2half2(__float2half_rn(a.x), __float2half_rn(a.y));
    *(__half2*)(dst + i + 2) = __halves2half2(__float2half_rn(a.z), __float2half_rn(a.w));
    *(__half2*)(dst + i + 4) = __halves2half2(__float2half_rn(b.x), __float2half_rn(b.y));
    *(__half2*)(dst + i + 6) = __halves2half2(__float2half_rn(b.z), __float2half_rn(b.w));
}

// ---------------------------------------------------------------------------
// kv via mma: per (bh, 1/4 split of 1024 tokens): kv[64d][64e] = k^T v;
// ksum side reduction. Partials stored fp16. 256 blocks = one wave.
// ---------------------------------------------------------------------------
__device__ __forceinline__ void kv_load_stage(uint32_t sb, size_t gbase, int tid) {
#pragma unroll
    for (int t = 0; t < 2; t++) {
        int u = t * 256 + tid;
        int row = u >> 3, cb = u & 7;
        uint32_t so = SWZ((uint32_t)(row * 128 + cb * 16));
        size_t g = gbase + (size_t)row * HD + cb * 8;
        cp16(sb + so, g_k16 + g);
        cp16(sb + 8192 + so, g_v + g);
    }
}

__global__ __launch_bounds__(256, 2) void kv_mma_kernel() {
    extern __shared__ char smem[];
    const uint32_t sm32 = smem_u32(smem);
    const int tid = threadIdx.x, lane = tid & 31, wid = tid >> 5;
    const int bh = blockIdx.x >> 2, sp = blockIdx.x & 3;
    const int wm = wid & 1, wn = wid >> 1;
    const size_t nbase = (size_t)bh * NTOK + sp * KV_TOK;

    float acc[2][2][4];
#pragma unroll
    for (int i = 0; i < 2; i++)
#pragma unroll
        for (int j = 0; j < 2; j++)
#pragma unroll
            for (int k = 0; k < 4; k++) acc[i][j][k] = 0.f;
    float ksacc = 0.f;
    const int ks_d = tid & 63, ks_q = tid >> 6;

    kv_load_stage(sm32, nbase * HD, tid);
    CP_COMMIT();

    const int l7 = lane & 7, lg = lane >> 3;
    const int an_off = ((lg >> 1) ? 8 : 0) + l7;
    const int ad_off = (lg & 1) ? 8 : 0;
    const int bn_off = ((lg & 1) ? 8 : 0) + l7;
    const int be_off = (lg >> 1) ? 8 : 0;
    const int d0 = wm * 32;
    const int e0 = wn * 16;

    for (int c = 0; c < KV_NCH; c++) {
        CP_WAIT0();
        __syncthreads();
        if (c + 1 < KV_NCH) {
            kv_load_stage(sm32 + ((c + 1) & 1) * KV_STAGE,
                          (nbase + (size_t)(c + 1) * 64) * HD, tid);
            CP_COMMIT();
        }
        const uint32_t sb = sm32 + (c & 1) * KV_STAGE;
#pragma unroll
        for (int kk = 0; kk < 64; kk += 16) {
            uint32_t ak[2][4], bv[4];
#pragma unroll
            for (int ma = 0; ma < 2; ma++) {
                uint32_t ad = SWZ((uint32_t)((kk + an_off) * 128 +
                                             (d0 + ma * 16 + ad_off) * 2));
                ldm4t(ak[ma], sb + ad);
            }
            uint32_t bd = SWZ((uint32_t)((kk + bn_off) * 128 + (e0 + be_off) * 2));
            ldm4t(bv, sb + 8192 + bd);
#pragma unroll
            for (int ma = 0; ma < 2; ma++)
#pragma unroll
                for (int nb = 0; nb < 2; nb++)
                    mma16816(acc[ma][nb], ak[ma], bv[nb * 2], bv[nb * 2 + 1]);
        }
#pragma unroll
        for (int nn = 0; nn < 16; nn++) {
            int n = ks_q * 16 + nn;
            uint32_t off = SWZ((uint32_t)(n * 128 + ks_d * 2));
            ksacc += __half2float(*(const __half*)(smem + (c & 1) * KV_STAGE + off));
        }
    }

    float* kssm = (float*)(smem + 2 * KV_STAGE);
    kssm[ks_q * 64 + ks_d] = ksacc;
    __syncthreads();
    if (tid < 64) {
        float s = kssm[tid] + kssm[64 + tid] + kssm[128 + tid] + kssm[192 + tid];
        g_ksum_part[(sp * NBH + bh) * HD + tid] = s;
    }

    const int r0 = lane >> 2, c0 = (lane & 3) * 2;
    __half* kvout = g_kv_part + (size_t)(sp * NBH + bh) * (HD * HD);
#pragma unroll
    for (int ma = 0; ma < 2; ma++)
#pragma unroll
        for (int nb = 0; nb < 2; nb++)
#pragma unroll
            for (int hf = 0; hf < 2; hf++) {
                int d = d0 + ma * 16 + r0 + hf * 8;
                int e = e0 + nb * 8 + c0;
                *(__half2*)(kvout + d * 64 + e) =
                    __halves2half2(__float2half_rn(acc[ma][nb][hf * 2]),
                                   __float2half_rn(acc[ma][nb][hf * 2 + 1]));
            }
}

// ---------------------------------------------------------------------------
// kv reduce: 8 blocks per bh; each reduces 512 elements (an 8-row d-band)
// with half2-vectorized partial loads. Band 0 also reduces ksum.
// ---------------------------------------------------------------------------
__global__ __launch_bounds__(256) void kv_reduce_kernel() {
    const int bh = blockIdx.x >> 3;
    const int qr = blockIdx.x & 7;
    const int tid = threadIdx.x;
    const int jbase = qr * 512;           // d band: [qr*8, qr*8+8)

    __shared__ float kvsm[8][65];

    {
        // 512 elems = 256 half2; one half2 per thread
        int jj = tid * 2;
        int j = jbase + jj;
        float s0 = 0.f, s1 = 0.f;
#pragma unroll
        for (int p = 0; p < KVSPLIT; p++) {
            __half2 hv = *(const __half2*)(g_kv_part +
                            (size_t)(p * NBH + bh) * (HD * HD) + j);
            float2 fv = __half22float2(hv);
            s0 += fv.x;
            s1 += fv.y;
        }
        kvsm[jj >> 6][jj & 63] = s0;
        kvsm[jj >> 6][(jj & 63) + 1] = s1;
    }
    if (qr == 0 && tid < HD) {
        float s = 0.f;
#pragma unroll
        for (int p = 0; p < KVSPLIT; p++)
            s += g_ksum_part[(p * NBH + bh) * HD + tid];
        g_ksum[bh * HD + tid] = s;
    }
    __syncthreads();
    for (int jj = tid; jj < 512; jj += 256) {
        int dl = jj >> 6;
        int e = jj & 63;
        int d = qr * 8 + dl;
        g_kvT[(size_t)bh * (HD * HD) + e * HD + d] = __float2half_rn(kvsm[dl][e]);
    }
}

// ---------------------------------------------------------------------------
// attn via mma: num = q @ kvT^T; /(q.ksum+eps); writes attn fp16.
// ---------------------------------------------------------------------------
__global__ __launch_bounds__(256, 2) void attn_mma_kernel() {
    extern __shared__ char smem[];
    const uint32_t sm32 = smem_u32(smem);
    const int tid = threadIdx.x, lane = tid & 31, wid = tid >> 5;
    const int bh = blockIdx.y;
    const int bb = bh >> 4, h = bh & 15;
    const int row0 = blockIdx.x * 128;
    const int wm = wid & 3, wn = wid >> 2;

    {
        size_t qbase = ((size_t)bh * NTOK + row0) * HD;
#pragma unroll
        for (int t = 0; t < 4; t++) {
            int u = t * 256 + tid;
            int row = u >> 3, cb = u & 7;
            uint32_t so = SWZ((uint32_t)(row * 128 + cb * 16));
            cp16(sm32 + AT_Q + so, g_q16 + qbase + (size_t)row * HD + cb * 8);
        }
#pragma unroll
        for (int t = 0; t < 2; t++) {
            int u = t * 256 + tid;
            int row = u >> 3, cb = u & 7;
            uint32_t so = SWZ((uint32_t)(row * 128 + cb * 16));
            cp16(sm32 + AT_KV + so,
                 g_kvT + (size_t)bh * (HD * HD) + (size_t)row * HD + cb * 8);
        }
        if (tid < 64) ((float*)(smem + AT_KSUM))[tid] = g_ksum[bh * HD + tid];
        CP_COMMIT();
        CP_WAIT0();
        __syncthreads();
    }

    {
        int row = tid >> 1, hh = tid & 1;
        float s = 0.f;
        const float* kss = (const float*)(smem + AT_KSUM);
#pragma unroll
        for (int dd = 0; dd < 32; dd++) {
            int d = hh * 32 + dd;
            uint32_t off = SWZ((uint32_t)(row * 128 + d * 2));
            s += __half2float(*(const __half*)(smem + AT_Q + off)) * kss[d];
        }
        s += __shfl_xor_sync(0xFFFFFFFFu, s, 1);
        if (hh == 0) ((float*)(smem + AT_INV))[row] = 1.f / (s + 1e-8f);
        __syncthreads();
    }

    float acc[2][4][4];
#pragma unroll
    for (int i = 0; i < 2; i++)
#pragma unroll
        for (int j = 0; j < 4; j++)
#pragma unroll
            for (int k = 0; k < 4; k++) acc[i][j][k] = 0.f;

    const int a_row = lane & 15;
    const int a_koff = (lane & 16) ? 8 : 0;
    const int b_row = (lane & 7) + ((lane & 16) >> 1);
    const int b_koff = (lane & 8) ? 8 : 0;

#pragma unroll
    for (int kk = 0; kk < 64; kk += 16) {
        uint32_t qa[2][4], kvb[2][4];
#pragma unroll
        for (int ma = 0; ma < 2; ma++) {
            uint32_t ad = SWZ((uint32_t)((wm * 32 + ma * 16 + a_row) * 128 +
                                         (kk + a_koff) * 2));
            ldm4(qa[ma], sm32 + AT_Q + ad);
        }
#pragma unroll
        for (int nb = 0; nb < 2; nb++) {
            uint32_t bd = SWZ((uint32_t)((wn * 32 + nb * 16 + b_row) * 128 +
                                         (kk + b_koff) * 2));
            ldm4(kvb[nb], sm32 + AT_KV + bd);
        }
#pragma unroll
        for (int ma = 0; ma < 2; ma++)
#pragma unroll
            for (int na = 0; na < 4; na++)
                mma16816(acc[ma][na], qa[ma],
                         kvb[na >> 1][(na & 1) * 2], kvb[na >> 1][(na & 1) * 2 + 1]);
    }

    const int r0 = lane >> 2, c0 = (lane & 3) * 2;
    const float* invp = (const float*)(smem + AT_INV);
#pragma unroll
    for (int ma = 0; ma < 2; ma++)
#pragma unroll
        for (int na = 0; na < 4; na++)
#pragma unroll
            for (int hf = 0; hf < 2; hf++) {
                int row = wm * 32 + ma * 16 + r0 + hf * 8;
                float iv = invp[row];
                int e = wn * 32 + na * 8 + c0;
                float v0 = acc[ma][na][hf * 2 + 0] * iv;
                float v1 = acc[ma][na][hf * 2 + 1] * iv;
                size_t ob = ((size_t)(bb * NTOK + row0 + row)) * CDIM + h * HD + e;
                *(__half2*)(g_attn + ob) =
                    __halves2half2(__float2half_rn(v0), __float2half_rn(v1));
            }
}

// ---------------------------------------------------------------------------
extern "C" void kernel_launch(void* const* d_in, const int* in_sizes, int n_in,
                              void* d_out, int out_size) {
    const float* x      = (const float*)d_in[0];
    const float* w_qkv  = (const float*)d_in[1];
    const float* w_proj = (const float*)d_in[2];
    const float* b_proj = (const float*)d_in[3];
    float* out = (float*)d_out;

    cudaFuncSetAttribute(gemm_qkv_mma, cudaFuncAttributeMaxDynamicSharedMemorySize,
                         SMEM_GEMM_BYTES);
    cudaFuncSetAttribute(gemm_proj_mma, cudaFuncAttributeMaxDynamicSharedMemorySize,
                         SMEM_GEMM_BYTES);
    cudaFuncSetAttribute(kv_mma_kernel, cudaFuncAttributeMaxDynamicSharedMemorySize,
                         SMEM_KV_BYTES);
    cudaFuncSetAttribute(attn_mma_kernel, cudaFuncAttributeMaxDynamicSharedMemorySize,
                         SMEM_AT_BYTES);

    conv16_fused_kernel<<<(CVT_TOT_V8 + 255) / 256, 256>>>(x, w_qkv, w_proj);

    gemm_qkv_mma<<<dim3(NQKV / BN, MTOT / BM), 256, SMEM_GEMM_BYTES>>>();

    kv_mma_kernel<<<NBH * KVSPLIT, 256, SMEM_KV_BYTES>>>();
    kv_reduce_kernel<<<NBH * 8, 256>>>();

    attn_mma_kernel<<<dim3(NTOK / 128, NBH), 256, SMEM_AT_BYTES>>>();

    gemm_proj_mma<<<dim3(CDIM / BN, MTOT / BM), 256, SMEM_GEMM_BYTES>>>(b_proj, out);
}